// round 12
// baseline (speedup 1.0000x reference)
#include <cuda_runtime.h>
#include <math.h>
#include <stdint.h>

// GeoFeaturizer for GB300 (sm_103a). B=8 batches, K=3 virtual frames (fixed).
#define NB 8
#define KF 3
#define TILE 32        // edges per edge-block (8 threads per edge, blockDim=256)
#define NTILE 64       // nodes per node-block
#define EW 213         // edge feature width
#define NFB 888        // fill/misc blocks
#define BLK 256

// pos-embedding freqs: 10000^(-j/8) = 10^(-j/2)
__constant__ float c_posfreq[8] = {
    1.0f, 0.31622776601683794f, 0.1f, 0.031622776601683794f,
    0.01f, 0.0031622776601683794f, 0.001f, 0.00031622776601683794f
};

// ---- TMA bulk-store helpers (smem -> gmem, L1-bypassing) ----
__device__ __forceinline__ void tma_bulk_store(void* gptr, uint32_t saddr, uint32_t bytes) {
    asm volatile("cp.async.bulk.global.shared::cta.bulk_group [%0], [%1], %2;"
                 :: "l"(gptr), "r"(saddr), "r"(bytes) : "memory");
}
__device__ __forceinline__ void tma_fence() {
    asm volatile("fence.proxy.async.shared::cta;" ::: "memory");
}
__device__ __forceinline__ void tma_commit() {
    asm volatile("cp.async.bulk.commit_group;" ::: "memory");
}
__device__ __forceinline__ void tma_wait_read0() {
    asm volatile("cp.async.bulk.wait_group.read 0;" ::: "memory");
}

// decouple() for a 3-vector: 3 direction comps + 16 RBF of the norm. All f32 fast-path.
__device__ __forceinline__ void dec3(float* __restrict__ w, float x, float y, float z) {
    float sq   = x*x + y*y + z*z;
    float norm = sqrtf(sq + 1e-12f);
    float inv  = (norm < 1e-4f) ? 0.f : __fdividef(1.f, norm + 1e-6f);
    w[0] = x * inv; w[1] = y * inv; w[2] = z * inv;
    float a = 0.8f * norm;
#pragma unroll
    for (int r = 0; r < 16; r++) {
        float u = a - (float)r * 1.0666666666666667f;
        w[3 + r] = __expf(-u * u);
    }
}

// f32 Cody-Waite reduction then fast sin/cos (|ang| <= ~3.2e4).
__device__ __forceinline__ void fast_sincos(float ang, float* s, float* c) {
    const float INV2PI = 0.15915494309189535f;
    const float PI2_HI = 6.28318548202514648f;
    const float PI2_LO = -1.74845553146357e-07f;
    float k = rintf(ang * INV2PI);
    float r = fmaf(-k, PI2_HI, ang);
    r = fmaf(-k, PI2_LO, r);
    *s = __sinf(r);
    *c = __cosf(r);
}

// Frame from atoms 0,1,2 (N, CA, C). R is the reference's stored R (= M^T).
__device__ __forceinline__ void make_frame(const float a0[3], const float a1[3], const float a2[3],
                                           float R[3][3]) {
    float nx = a0[0] - a1[0], ny_ = a0[1] - a1[1], nz_ = a0[2] - a1[2];
    float cx = a2[0] - a1[0], cy  = a2[1] - a1[1], cz  = a2[2] - a1[2];
    const float EPSf = 1e-20f;
    float nrm  = sqrtf(EPSf + cx*cx + cy*cy);
    float s1 = -cy / nrm, c1 = cx / nrm;
    float nrm2 = sqrtf(EPSf + cx*cx + cy*cy + cz*cz);
    float s2 = cz / nrm2;
    float c2 = sqrtf(cx*cx + cy*cy) / nrm2;
    float Rc[3][3] = {
        { c2*c1, -c2*s1, s2 },
        { s1,     c1,    0.f},
        {-s2*c1,  s2*s1, c2 }
    };
    float nr1 = Rc[1][0]*nx + Rc[1][1]*ny_;
    float nr2 = Rc[2][0]*nx + Rc[2][1]*ny_ + Rc[2][2]*nz_;
    float nrm3 = sqrtf(EPSf + nr1*nr1 + nr2*nr2);
    float sn = -nr2 / nrm3, cn = nr1 / nrm3;
    float M1[3], M2[3];
#pragma unroll
    for (int j = 0; j < 3; j++) {
        M1[j] = cn * Rc[1][j] - sn * Rc[2][j];
        M2[j] = sn * Rc[1][j] + cn * Rc[2][j];
    }
#pragma unroll
    for (int j = 0; j < 3; j++) {
        R[j][0] = Rc[0][j];
        R[j][1] = M1[j];
        R[j][2] = M2[j];
    }
}

// edge smem layout (floats): [0, TILE*EW) rows; TILE*9 rot; TILE*3 trans
#define SM_ROT   (TILE * EW)
#define SM_TRANS (SM_ROT + TILE * 9)
#define SM_TOTAL (SM_TRANS + TILE * 3)      // 7200 floats = 28800 B

// node smem layout (floats)
#define SV_V     0
#define SV_TROT  (NTILE * 76)               // 4864
#define SV_TTR   (SV_TROT + NTILE * 9)      // 5440
#define SV_B     (SV_TTR + NTILE * 3)       // 5632
#define SV_C     (SV_B + NTILE)             // 5696  (end 5760)

// ---------------------------------------------------------------------------
__global__ void __launch_bounds__(BLK, 6)
fused_kernel(const float* __restrict__ X,
             const int*  __restrict__ node_idx,
             const int*  __restrict__ eix,       // (2, E) row-major
             const int*  __restrict__ batch_id,
             const int*  __restrict__ chain,
             float* __restrict__ out,
             int N, int E, int nEB, int nNB,
             long long OFF_V, long long OFF_E, long long OFF_TROT,
             long long OFF_TTRANS, long long OFF_TTSROT, long long OFF_TTSTRANS,
             long long OFF_BATCH, long long OFF_EIDX, long long OFF_CHAIN) {
    extern __shared__ float sm[];
    int tid = threadIdx.x;
    int bid = blockIdx.x;
    const int ET = E + 2 * KF * N;
    uint32_t smBase = (uint32_t)__cvta_generic_to_shared(sm);

    if (bid < nEB) {
        // ------------------------------------------------ edge role (E % TILE == 0)
        int eSlot = tid >> 3;          // 0..31
        int sub   = tid & 7;           // 0..7
        int e0 = bid * TILE;
        int e  = e0 + eSlot;

        {
            float* w = sm + eSlot * EW;
            int s = min(max(eix[e], 0), N - 1);
            int d = min(max(eix[E + e], 0), N - 1);

            const float4* Xs4 = reinterpret_cast<const float4*>(X) + (size_t)s * 3;
            const float4* Xd4 = reinterpret_cast<const float4*>(X) + (size_t)d * 3;
            float4 sa = Xs4[0], sb = Xs4[1], sc = Xs4[2];
            float4 da = Xd4[0], db = Xd4[1], dc = Xd4[2];
            float P[8][3] = {
                {sa.x, sa.y, sa.z}, {sa.w, sb.x, sb.y}, {sb.z, sb.w, sc.x}, {sc.y, sc.z, sc.w},
                {da.x, da.y, da.z}, {da.w, db.x, db.y}, {db.z, db.w, dc.x}, {dc.y, dc.z, dc.w}
            };

            float Rs[3][3];
            make_frame(P[0], P[1], P[2], Rs);
            float ts[3] = {P[1][0], P[1][1], P[1][2]};

            // each sub: its own atom dec3 (cols 0..151)
            {
                int a8 = sub;
                float q0 = P[a8][0] - ts[0], q1 = P[a8][1] - ts[1], q2 = P[a8][2] - ts[2];
                float l0 = Rs[0][0]*q0 + Rs[1][0]*q1 + Rs[2][0]*q2;
                float l1 = Rs[0][1]*q0 + Rs[1][1]*q1 + Rs[2][1]*q2;
                float l2 = Rs[0][2]*q0 + Rs[1][2]*q1 + Rs[2][2]*q2;
                dec3(w + a8 * 19, l0, l1, l2);
            }

            if (sub == 0) {
                // Q = Rs^T Rd; E_quant (cols 152..160) = Q; Tts_rot staging = Q^T
                float Rd[3][3];
                make_frame(P[4], P[5], P[6], Rd);
                float Q[3][3];
#pragma unroll
                for (int i = 0; i < 3; i++)
#pragma unroll
                    for (int j = 0; j < 3; j++)
                        Q[i][j] = Rs[0][i]*Rd[0][j] + Rs[1][i]*Rd[1][j] + Rs[2][i]*Rd[2][j];
#pragma unroll
                for (int i = 0; i < 3; i++)
#pragma unroll
                    for (int j = 0; j < 3; j++) {
                        w[152 + 3 * i + j] = Q[i][j];
                        sm[SM_ROT + eSlot * 9 + 3 * j + i] = Q[i][j];
                    }
            } else if (sub == 1) {
                // tts = Rd^T (t_src - t_dst); stage Tts_trans
                float Rd[3][3];
                make_frame(P[4], P[5], P[6], Rd);
                float dt0 = ts[0] - P[5][0], dt1 = ts[1] - P[5][1], dt2 = ts[2] - P[5][2];
                float t0 = Rd[0][0]*dt0 + Rd[1][0]*dt1 + Rd[2][0]*dt2;
                float t1 = Rd[0][1]*dt0 + Rd[1][1]*dt1 + Rd[2][1]*dt2;
                float t2 = Rd[0][2]*dt0 + Rd[1][2]*dt1 + Rd[2][2]*dt2;
                sm[SM_TRANS + eSlot * 3 + 0] = t0;
                sm[SM_TRANS + eSlot * 3 + 1] = t1;
                sm[SM_TRANS + eSlot * 3 + 2] = t2;
            } else if (sub == 2) {
                // E_trans (cols 161..179) = dec3 of tts (recompute Rd + tts)
                float Rd[3][3];
                make_frame(P[4], P[5], P[6], Rd);
                float dt0 = ts[0] - P[5][0], dt1 = ts[1] - P[5][1], dt2 = ts[2] - P[5][2];
                float t0 = Rd[0][0]*dt0 + Rd[1][0]*dt1 + Rd[2][0]*dt2;
                float t1 = Rd[0][1]*dt0 + Rd[1][1]*dt1 + Rd[2][1]*dt2;
                float t2 = Rd[0][2]*dt0 + Rd[1][2]*dt1 + Rd[2][2]*dt2;
                dec3(w + 161, t0, t1, t2);
            } else if (sub == 3) {
                // pos embedding j=0..3 (cols 180..183, 188..191)
                float dd = (float)(s - d);
#pragma unroll
                for (int j = 0; j < 4; j++) {
                    float ang = __fmul_rn(dd, c_posfreq[j]);
                    float si, co;
                    fast_sincos(ang, &si, &co);
                    w[180 + j] = co;
                    w[188 + j] = si;
                }
            } else if (sub == 4) {
                // pos embedding j=4..7
                float dd = (float)(s - d);
#pragma unroll
                for (int j = 4; j < 8; j++) {
                    float ang = __fmul_rn(dd, c_posfreq[j]);
                    float si, co;
                    fast_sincos(ang, &si, &co);
                    w[180 + j] = co;
                    w[188 + j] = si;
                }
            } else if (sub == 5) {
                // E_bias (cols 196..212)
                float bb = (float)(node_idx[s] - node_idx[d]);
                float nb = sqrtf(bb * bb + 1e-12f);
                float ib = (nb < 1e-4f) ? 0.f : __fdividef(1.f, nb + 1e-6f);
                w[196] = bb * ib;
                float ab = 0.8f * nb;
#pragma unroll
                for (int r = 0; r < 16; r++) {
                    float u = ab - (float)r * 1.0666666666666667f;
                    w[197 + r] = __expf(-u * u);
                }
            } else if (sub == 6) {
                out[OFF_EIDX + e]      = (float)eix[e];
                out[OFF_EIDX + ET + e] = (float)eix[E + e];
            }
        }
        __syncthreads();

        if (tid == 0) {
            tma_fence();
            tma_bulk_store(out + OFF_E + (long long)e0 * EW,       smBase,                  TILE * EW * 4u);
            tma_bulk_store(out + OFF_TTSROT + (long long)e0 * 9,   smBase + SM_ROT * 4u,    TILE * 9 * 4u);
            tma_bulk_store(out + OFF_TTSTRANS + (long long)e0 * 3, smBase + SM_TRANS * 4u,  TILE * 3 * 4u);
            tma_commit();
            tma_wait_read0();
        }
    } else if (bid < nEB + nNB) {
        // ------------------------------------------------ node role (64 nodes/block)
        int n0 = (bid - nEB) * NTILE;
        int n  = n0 + tid;
        int rem = min(NTILE, N - n0);

        if (tid < NTILE && n < N) {
            const float4* X4 = reinterpret_cast<const float4*>(X) + (size_t)n * 3;
            float4 xa = X4[0], xb = X4[1], xc = X4[2];
            float ax[4][3] = {
                {xa.x, xa.y, xa.z}, {xa.w, xb.x, xb.y},
                {xb.z, xb.w, xc.x}, {xc.y, xc.z, xc.w}
            };
            float R[3][3];
            make_frame(ax[0], ax[1], ax[2], R);

#pragma unroll
            for (int i = 0; i < 3; i++)
#pragma unroll
                for (int j = 0; j < 3; j++)
                    sm[SV_TROT + tid * 9 + 3 * i + j] = R[i][j];
            sm[SV_TTR + tid * 3 + 0] = ax[1][0];
            sm[SV_TTR + tid * 3 + 1] = ax[1][1];
            sm[SV_TTR + tid * 3 + 2] = ax[1][2];
            sm[SV_B + tid] = (float)batch_id[n];
            sm[SV_C + tid] = (float)chain[n];

            bool start = (n == 0) || (batch_id[n] != batch_id[n - 1]);
            float prev0 = 0.f, prev1 = 0.f, prev2 = 0.f;
            if (n > 0) {
                const float* xp = X + (size_t)(n - 1) * 12 + 9;
                prev0 = xp[0]; prev1 = xp[1]; prev2 = xp[2];
            }
            float* wv = sm + SV_V + tid * 76;
#pragma unroll
            for (int a = 0; a < 4; a++) {
                float dx, dy, dz;
                if (start) { dx = dy = dz = 0.f; }
                else {
                    float px, py, pz;
                    if (a == 0) { px = prev0; py = prev1; pz = prev2; }
                    else        { px = ax[a-1][0]; py = ax[a-1][1]; pz = ax[a-1][2]; }
                    dx = ax[a][0] - px; dy = ax[a][1] - py; dz = ax[a][2] - pz;
                }
                float l0 = R[0][0]*dx + R[1][0]*dy + R[2][0]*dz;
                float l1 = R[0][1]*dx + R[1][1]*dy + R[2][1]*dz;
                float l2 = R[0][2]*dx + R[1][2]*dy + R[2][2]*dz;
                dec3(wv + a * 19, l0, l1, l2);
            }
        }
        __syncthreads();

        if (tid == 0 && rem > 0) {
            tma_fence();
            tma_bulk_store(out + OFF_V + (long long)n0 * 76,     smBase + SV_V * 4u,    (uint32_t)(rem * 76 * 4));
            tma_bulk_store(out + OFF_TROT + (long long)n0 * 9,   smBase + SV_TROT * 4u, (uint32_t)(rem * 9 * 4));
            tma_bulk_store(out + OFF_TTRANS + (long long)n0 * 3, smBase + SV_TTR * 4u,  (uint32_t)(rem * 3 * 4));
            tma_bulk_store(out + OFF_BATCH + n0,                 smBase + SV_B * 4u,    (uint32_t)(rem * 4));
            tma_bulk_store(out + OFF_CHAIN + n0,                 smBase + SV_C * 4u,    (uint32_t)(rem * 4));
            tma_commit();
            tma_wait_read0();
        }
    } else {
        // ------------------------------------------------ fill + misc role
        const unsigned KN = KF * (unsigned)N, G2 = 2u * KN, uET = (unsigned)E + G2, KB = KF * NB;
        const unsigned zelems = G2 * (unsigned)EW;
        const unsigned CHUNKF = TILE * EW;                       // 6816 floats = 27264 B
        const unsigned nChunk = zelems / CHUNKF;
        const unsigned tailF  = zelems - nChunk * CHUNKF;        // mult of 4
        const long long zbase = OFF_E + (long long)E * EW;

        unsigned fb = (unsigned)(bid - nEB - nNB);

        for (int i = tid; i < (int)CHUNKF; i += BLK) sm[i] = 0.f;
        __syncthreads();

        if (tid == 0) {
            tma_fence();
            for (unsigned c = fb; c < nChunk; c += NFB)
                tma_bulk_store(out + zbase + (long long)c * CHUNKF, smBase, CHUNKF * 4u);
            if (fb == 0 && tailF)
                tma_bulk_store(out + zbase + (long long)nChunk * CHUNKF, smBase, tailF * 4u);
            tma_commit();
        }

        // misc tails
        const unsigned szA = G2 * 9u;
        const unsigned szB = G2 * 3u;
        const unsigned szC = 2u * G2;
        const unsigned szD = KB;
        const unsigned szE_ = KB;
        const unsigned szF = KB * 9u;
        const unsigned szG = KB * 3u;
        const unsigned szH = KB * 76u;
        const unsigned TOT = szA + szB + szC + szD + szE_ + szF + szG + szH;

        const unsigned bTTSROT = (unsigned)OFF_TTSROT + (unsigned)E * 9u;
        const unsigned bTTSTR  = (unsigned)OFF_TTSTRANS + (unsigned)E * 3u;
        const unsigned bEIDX   = (unsigned)OFF_EIDX;
        const unsigned bBATCH  = (unsigned)OFF_BATCH + (unsigned)N;
        const unsigned bCHAIN  = (unsigned)OFF_CHAIN + (unsigned)N;
        const unsigned bTROT   = (unsigned)OFF_TROT + (unsigned)N * 9u;
        const unsigned bTTRANS = (unsigned)OFF_TTRANS + (unsigned)N * 3u;
        const unsigned bV      = (unsigned)OFF_V + (unsigned)N * 76u;
        const unsigned uN = (unsigned)N, uE = (unsigned)E;

        unsigned stride = (unsigned)NFB * BLK;
        for (unsigned j0 = fb * BLK + tid; j0 < TOT; j0 += stride) {
            unsigned j = j0;
            unsigned idx; float v;
            if (j < szA) {
                unsigned c = j % 9u;
                idx = bTTSROT + j; v = (c == 0u || c == 4u || c == 8u) ? 1.f : 0.f;
            } else if ((j -= szA) < szB) {
                idx = bTTSTR + j; v = 0.f;
            } else if ((j -= szB) < szC) {
                if (j < G2) {
                    v = (j < KN) ? (float)(uN + (unsigned)batch_id[j % uN] + (j / uN) * NB)
                                 : (float)((j - KN) % uN);
                    idx = bEIDX + uE + j;
                } else {
                    unsigned t = j - G2;
                    v = (t < KN) ? (float)(t % uN)
                                 : (float)(uN + (unsigned)batch_id[(t - KN) % uN] + ((t - KN) / uN) * NB);
                    idx = bEIDX + uET + uE + t;
                }
            } else if ((j -= szC) < szD) {
                idx = bBATCH + j; v = (float)(j % NB);
            } else if ((j -= szD) < szE_) {
                idx = bCHAIN + j; v = 1001.f;
            } else if ((j -= szE_) < szF) {
                unsigned c = j % 9u;
                idx = bTROT + j; v = (c == 0u || c == 4u || c == 8u) ? 1.f : 0.f;
            } else if ((j -= szF) < szG) {
                idx = bTTRANS + j; v = 0.f;
            } else {
                j -= szG;
                unsigned r = j / 76u, c = j % 76u;
                unsigned k = r / NB;
                unsigned m = (c < 38u) ? c : c - 38u;
                double f = exp(-(double)(2u * m) * 9.210340371976184 / 76.0);
                double ang = (double)k * f;
                idx = bV + j; v = (float)((c < 38u) ? cos(ang) : sin(ang));
            }
            out[idx] = v;
        }

        if (tid == 0) tma_wait_read0();
    }
}

// ---------------------------------------------------------------------------
extern "C" void kernel_launch(void* const* d_in, const int* in_sizes, int n_in,
                              void* d_out, int out_size) {
    const float* X        = (const float*)d_in[0];
    const int*   node_idx = (const int*)d_in[1];
    const int*   eix      = (const int*)d_in[2];
    const int*   batch_id = (const int*)d_in[3];
    const int*   chain    = (const int*)d_in[4];
    float* out = (float*)d_out;

    int N = in_sizes[0] / 12;
    int E = in_sizes[2] / 2;
    int NT = N + KF * NB;
    int G2 = 2 * KF * N;
    int ET = E + G2;

    long long OFF_V        = 0;
    long long OFF_E        = OFF_V + (long long)NT * 76;
    long long OFF_TROT     = OFF_E + (long long)ET * EW;
    long long OFF_TTRANS   = OFF_TROT + (long long)NT * 9;
    long long OFF_TTSROT   = OFF_TTRANS + (long long)NT * 3;
    long long OFF_TTSTRANS = OFF_TTSROT + (long long)ET * 9;
    long long OFF_BATCH    = OFF_TTSTRANS + (long long)ET * 3;
    long long OFF_EIDX     = OFF_BATCH + NT;
    long long OFF_CHAIN    = OFF_EIDX + 2LL * ET;

    int nEB = (E + TILE - 1) / TILE;   // E divisible by TILE
    int nNB = (N + NTILE - 1) / NTILE;
    int grid = nEB + nNB + NFB;
    int smem = SM_TOTAL * (int)sizeof(float);   // 28800 B

    static bool attr_done = false;
    if (!attr_done) {
        cudaFuncSetAttribute(fused_kernel, cudaFuncAttributeMaxDynamicSharedMemorySize, smem);
        attr_done = true;
    }

    fused_kernel<<<grid, BLK, smem>>>(X, node_idx, eix, batch_id, chain, out,
                                      N, E, nEB, nNB,
                                      OFF_V, OFF_E, OFF_TROT, OFF_TTRANS,
                                      OFF_TTSROT, OFF_TTSTRANS,
                                      OFF_BATCH, OFF_EIDX, OFF_CHAIN);
}

// round 13
// speedup vs baseline: 1.4306x; 1.4306x over previous
#include <cuda_runtime.h>
#include <math.h>
#include <stdint.h>

// GeoFeaturizer for GB300 (sm_103a). B=8 batches, K=3 virtual frames (fixed).
#define NB 8
#define KF 3
#define TILE 32        // edges per edge-block (4 threads per edge, blockDim=128)
#define NTILE 64       // nodes per node-block
#define EW 213         // edge feature width
#define NFB 888        // fill/misc blocks (scheduled FIRST)

// pos-embedding freqs: 10000^(-j/8) = 10^(-j/2)
__constant__ float c_posfreq[8] = {
    1.0f, 0.31622776601683794f, 0.1f, 0.031622776601683794f,
    0.01f, 0.0031622776601683794f, 0.001f, 0.00031622776601683794f
};

// ---- TMA bulk-store helpers (smem -> gmem, L1-bypassing) ----
__device__ __forceinline__ void tma_bulk_store(void* gptr, uint32_t saddr, uint32_t bytes) {
    asm volatile("cp.async.bulk.global.shared::cta.bulk_group [%0], [%1], %2;"
                 :: "l"(gptr), "r"(saddr), "r"(bytes) : "memory");
}
__device__ __forceinline__ void tma_fence() {
    asm volatile("fence.proxy.async.shared::cta;" ::: "memory");
}
__device__ __forceinline__ void tma_commit() {
    asm volatile("cp.async.bulk.commit_group;" ::: "memory");
}
// wait until bulk ops have finished READING smem; gmem visibility at kernel end.
__device__ __forceinline__ void tma_wait_read0() {
    asm volatile("cp.async.bulk.wait_group.read 0;" ::: "memory");
}

// decouple() for a 3-vector: 3 direction comps + 16 RBF of the norm.
__device__ __forceinline__ void dec3(float* __restrict__ w, float x, float y, float z) {
    float sq   = x*x + y*y + z*z;
    float norm = sqrtf(sq + 1e-12f);
    float inv  = (norm < 1e-4f) ? 0.f : __fdividef(1.f, norm + 1e-6f);
    w[0] = x * inv; w[1] = y * inv; w[2] = z * inv;
    float a = 0.8f * norm;
#pragma unroll
    for (int r = 0; r < 16; r++) {
        float u = a - (float)r * 1.0666666666666667f;
        w[3 + r] = __expf(-u * u);
    }
}

// f32 Cody-Waite reduction then fast sin/cos (|ang| <= ~3.2e4).
__device__ __forceinline__ void fast_sincos(float ang, float* s, float* c) {
    const float INV2PI = 0.15915494309189535f;
    const float PI2_HI = 6.28318548202514648f;
    const float PI2_LO = -1.74845553146357e-07f;
    float k = rintf(ang * INV2PI);
    float r = fmaf(-k, PI2_HI, ang);
    r = fmaf(-k, PI2_LO, r);
    *s = __sinf(r);
    *c = __cosf(r);
}

// Frame from atoms 0,1,2 (N, CA, C). R is the reference's stored R (= M^T).
__device__ __forceinline__ void make_frame(const float a0[3], const float a1[3], const float a2[3],
                                           float R[3][3]) {
    float nx = a0[0] - a1[0], ny_ = a0[1] - a1[1], nz_ = a0[2] - a1[2];
    float cx = a2[0] - a1[0], cy  = a2[1] - a1[1], cz  = a2[2] - a1[2];
    const float EPSf = 1e-20f;
    float nrm  = sqrtf(EPSf + cx*cx + cy*cy);
    float s1 = -cy / nrm, c1 = cx / nrm;
    float nrm2 = sqrtf(EPSf + cx*cx + cy*cy + cz*cz);
    float s2 = cz / nrm2;
    float c2 = sqrtf(cx*cx + cy*cy) / nrm2;
    float Rc[3][3] = {
        { c2*c1, -c2*s1, s2 },
        { s1,     c1,    0.f},
        {-s2*c1,  s2*s1, c2 }
    };
    float nr1 = Rc[1][0]*nx + Rc[1][1]*ny_;
    float nr2 = Rc[2][0]*nx + Rc[2][1]*ny_ + Rc[2][2]*nz_;
    float nrm3 = sqrtf(EPSf + nr1*nr1 + nr2*nr2);
    float sn = -nr2 / nrm3, cn = nr1 / nrm3;
    float M1[3], M2[3];
#pragma unroll
    for (int j = 0; j < 3; j++) {
        M1[j] = cn * Rc[1][j] - sn * Rc[2][j];
        M2[j] = sn * Rc[1][j] + cn * Rc[2][j];
    }
#pragma unroll
    for (int j = 0; j < 3; j++) {
        R[j][0] = Rc[0][j];
        R[j][1] = M1[j];
        R[j][2] = M2[j];
    }
}

// edge smem layout (floats): [0, TILE*EW) rows; TILE*9 rot; TILE*3 trans
#define SM_ROT   (TILE * EW)
#define SM_TRANS (SM_ROT + TILE * 9)
#define SM_TOTAL (SM_TRANS + TILE * 3)      // 7200 floats = 28800 B

// node smem layout (floats)
#define SV_V     0
#define SV_TROT  (NTILE * 76)               // 4864
#define SV_TTR   (SV_TROT + NTILE * 9)      // 5440
#define SV_B     (SV_TTR + NTILE * 3)       // 5632
#define SV_C     (SV_B + NTILE)             // 5696  (end 5760)

// ---------------------------------------------------------------------------
// Role order by bid: [0,NFB) fill+misc  |  [NFB,NFB+nNB) node  |  rest edge.
// Fill first so the 155MB zero-region TMA writes drain concurrently with the
// edge compute phase instead of forming a serial tail.
// ---------------------------------------------------------------------------
__global__ void __launch_bounds__(128, 8)
fused_kernel(const float* __restrict__ X,
             const int*  __restrict__ node_idx,
             const int*  __restrict__ eix,       // (2, E) row-major
             const int*  __restrict__ batch_id,
             const int*  __restrict__ chain,
             float* __restrict__ out,
             int N, int E, int nEB, int nNB,
             long long OFF_V, long long OFF_E, long long OFF_TROT,
             long long OFF_TTRANS, long long OFF_TTSROT, long long OFF_TTSTRANS,
             long long OFF_BATCH, long long OFF_EIDX, long long OFF_CHAIN) {
    extern __shared__ float sm[];
    int tid = threadIdx.x;
    int bid = blockIdx.x;
    const int ET = E + 2 * KF * N;
    uint32_t smBase = (uint32_t)__cvta_generic_to_shared(sm);

    if (bid >= NFB + nNB) {
        // ------------------------------------------------ edge role (E % TILE == 0)
        int eSlot = tid >> 2;          // 0..31
        int sub   = tid & 3;           // 0..3
        int e0 = (bid - NFB - nNB) * TILE;
        int e  = e0 + eSlot;

        {
            float* w = sm + eSlot * EW;
            int s = min(max(eix[e], 0), N - 1);
            int d = min(max(eix[E + e], 0), N - 1);

            const float4* Xs4 = reinterpret_cast<const float4*>(X) + (size_t)s * 3;
            const float4* Xd4 = reinterpret_cast<const float4*>(X) + (size_t)d * 3;
            float4 sa = Xs4[0], sb = Xs4[1], sc = Xs4[2];
            float4 da = Xd4[0], db = Xd4[1], dc = Xd4[2];
            float P[8][3] = {
                {sa.x, sa.y, sa.z}, {sa.w, sb.x, sb.y}, {sb.z, sb.w, sc.x}, {sc.y, sc.z, sc.w},
                {da.x, da.y, da.z}, {da.w, db.x, db.y}, {db.z, db.w, dc.x}, {dc.y, dc.z, dc.w}
            };

            float Rs[3][3];
            make_frame(P[0], P[1], P[2], Rs);
            float ts[3] = {P[1][0], P[1][1], P[1][2]};

            // each sub: 2 of the 8 atom dec3s (cols 0..151)
#pragma unroll
            for (int k = 0; k < 2; k++) {
                int a8 = 2 * sub + k;
                float q0 = P[a8][0] - ts[0], q1 = P[a8][1] - ts[1], q2 = P[a8][2] - ts[2];
                float l0 = Rs[0][0]*q0 + Rs[1][0]*q1 + Rs[2][0]*q2;
                float l1 = Rs[0][1]*q0 + Rs[1][1]*q1 + Rs[2][1]*q2;
                float l2 = Rs[0][2]*q0 + Rs[1][2]*q1 + Rs[2][2]*q2;
                dec3(w + a8 * 19, l0, l1, l2);
            }

            if (sub == 0) {
                // Q = Rs^T Rd; E_quant (cols 152..160) = Q; Tts_rot staging = Q^T
                float Rd[3][3];
                make_frame(P[4], P[5], P[6], Rd);
                float Q[3][3];
#pragma unroll
                for (int i = 0; i < 3; i++)
#pragma unroll
                    for (int j = 0; j < 3; j++)
                        Q[i][j] = Rs[0][i]*Rd[0][j] + Rs[1][i]*Rd[1][j] + Rs[2][i]*Rd[2][j];
#pragma unroll
                for (int i = 0; i < 3; i++)
#pragma unroll
                    for (int j = 0; j < 3; j++) {
                        w[152 + 3 * i + j] = Q[i][j];
                        sm[SM_ROT + eSlot * 9 + 3 * j + i] = Q[i][j];
                    }
            } else if (sub == 1) {
                // tts = Rd^T (t_src - t_dst); E_trans (cols 161..179)
                float Rd[3][3];
                make_frame(P[4], P[5], P[6], Rd);
                float dt0 = ts[0] - P[5][0], dt1 = ts[1] - P[5][1], dt2 = ts[2] - P[5][2];
                float t0 = Rd[0][0]*dt0 + Rd[1][0]*dt1 + Rd[2][0]*dt2;
                float t1 = Rd[0][1]*dt0 + Rd[1][1]*dt1 + Rd[2][1]*dt2;
                float t2 = Rd[0][2]*dt0 + Rd[1][2]*dt1 + Rd[2][2]*dt2;
                dec3(w + 161, t0, t1, t2);
                sm[SM_TRANS + eSlot * 3 + 0] = t0;
                sm[SM_TRANS + eSlot * 3 + 1] = t1;
                sm[SM_TRANS + eSlot * 3 + 2] = t2;
            } else if (sub == 2) {
                // pos embedding (cols 180..195)
                float dd = (float)(s - d);
#pragma unroll
                for (int j = 0; j < 8; j++) {
                    float ang = __fmul_rn(dd, c_posfreq[j]);
                    float si, co;
                    fast_sincos(ang, &si, &co);
                    w[180 + j] = co;
                    w[188 + j] = si;
                }
            } else {
                // E_bias (cols 196..212) + eidx outputs
                float bb = (float)(node_idx[s] - node_idx[d]);
                float nb = sqrtf(bb * bb + 1e-12f);
                float ib = (nb < 1e-4f) ? 0.f : __fdividef(1.f, nb + 1e-6f);
                w[196] = bb * ib;
                float ab = 0.8f * nb;
#pragma unroll
                for (int r = 0; r < 16; r++) {
                    float u = ab - (float)r * 1.0666666666666667f;
                    w[197 + r] = __expf(-u * u);
                }
                out[OFF_EIDX + e]      = (float)eix[e];
                out[OFF_EIDX + ET + e] = (float)eix[E + e];
            }
        }
        __syncthreads();

        if (tid == 0) {
            tma_fence();
            tma_bulk_store(out + OFF_E + (long long)e0 * EW,       smBase,                  TILE * EW * 4u);
            tma_bulk_store(out + OFF_TTSROT + (long long)e0 * 9,   smBase + SM_ROT * 4u,    TILE * 9 * 4u);
            tma_bulk_store(out + OFF_TTSTRANS + (long long)e0 * 3, smBase + SM_TRANS * 4u,  TILE * 3 * 4u);
            tma_commit();
            tma_wait_read0();
        }
    } else if (bid >= NFB) {
        // ------------------------------------------------ node role (64 nodes/block)
        int n0 = (bid - NFB) * NTILE;
        int n  = n0 + tid;
        int rem = min(NTILE, N - n0);

        if (tid < NTILE && n < N) {
            const float4* X4 = reinterpret_cast<const float4*>(X) + (size_t)n * 3;
            float4 xa = X4[0], xb = X4[1], xc = X4[2];
            float ax[4][3] = {
                {xa.x, xa.y, xa.z}, {xa.w, xb.x, xb.y},
                {xb.z, xb.w, xc.x}, {xc.y, xc.z, xc.w}
            };
            float R[3][3];
            make_frame(ax[0], ax[1], ax[2], R);

#pragma unroll
            for (int i = 0; i < 3; i++)
#pragma unroll
                for (int j = 0; j < 3; j++)
                    sm[SV_TROT + tid * 9 + 3 * i + j] = R[i][j];
            sm[SV_TTR + tid * 3 + 0] = ax[1][0];
            sm[SV_TTR + tid * 3 + 1] = ax[1][1];
            sm[SV_TTR + tid * 3 + 2] = ax[1][2];
            sm[SV_B + tid] = (float)batch_id[n];
            sm[SV_C + tid] = (float)chain[n];

            bool start = (n == 0) || (batch_id[n] != batch_id[n - 1]);
            float prev0 = 0.f, prev1 = 0.f, prev2 = 0.f;
            if (n > 0) {
                const float* xp = X + (size_t)(n - 1) * 12 + 9;
                prev0 = xp[0]; prev1 = xp[1]; prev2 = xp[2];
            }
            float* wv = sm + SV_V + tid * 76;
#pragma unroll
            for (int a = 0; a < 4; a++) {
                float dx, dy, dz;
                if (start) { dx = dy = dz = 0.f; }
                else {
                    float px, py, pz;
                    if (a == 0) { px = prev0; py = prev1; pz = prev2; }
                    else        { px = ax[a-1][0]; py = ax[a-1][1]; pz = ax[a-1][2]; }
                    dx = ax[a][0] - px; dy = ax[a][1] - py; dz = ax[a][2] - pz;
                }
                float l0 = R[0][0]*dx + R[1][0]*dy + R[2][0]*dz;
                float l1 = R[0][1]*dx + R[1][1]*dy + R[2][1]*dz;
                float l2 = R[0][2]*dx + R[1][2]*dy + R[2][2]*dz;
                dec3(wv + a * 19, l0, l1, l2);
            }
        }
        __syncthreads();

        if (tid == 0 && rem > 0) {
            tma_fence();
            // rem is 64 or 48 here: all sizes multiples of 16B
            tma_bulk_store(out + OFF_V + (long long)n0 * 76,     smBase + SV_V * 4u,    (uint32_t)(rem * 76 * 4));
            tma_bulk_store(out + OFF_TROT + (long long)n0 * 9,   smBase + SV_TROT * 4u, (uint32_t)(rem * 9 * 4));
            tma_bulk_store(out + OFF_TTRANS + (long long)n0 * 3, smBase + SV_TTR * 4u,  (uint32_t)(rem * 3 * 4));
            tma_bulk_store(out + OFF_BATCH + n0,                 smBase + SV_B * 4u,    (uint32_t)(rem * 4));
            tma_bulk_store(out + OFF_CHAIN + n0,                 smBase + SV_C * 4u,    (uint32_t)(rem * 4));
            tma_commit();
            tma_wait_read0();
        }
    } else {
        // ------------------------------------------------ fill + misc role (FIRST)
        const unsigned KN = KF * (unsigned)N, G2 = 2u * KN, uET = (unsigned)E + G2, KB = KF * NB;
        const unsigned zelems = G2 * (unsigned)EW;               // zero-region floats
        const unsigned CHUNKF = TILE * EW;                       // 6816 floats = 27264 B
        const unsigned nChunk = zelems / CHUNKF;                 // full chunks
        const unsigned tailF  = zelems - nChunk * CHUNKF;        // mult of 4
        const long long zbase = OFF_E + (long long)E * EW;

        unsigned fb = (unsigned)bid;

        // zero the smem staging buffer once
        for (int i = tid; i < (int)CHUNKF; i += 128) sm[i] = 0.f;
        __syncthreads();

        if (tid == 0) {
            tma_fence();
            for (unsigned c = fb; c < nChunk; c += NFB)
                tma_bulk_store(out + zbase + (long long)c * CHUNKF, smBase, CHUNKF * 4u);
            if (fb == 0 && tailF)
                tma_bulk_store(out + zbase + (long long)nChunk * CHUNKF, smBase, tailF * 4u);
            tma_commit();
        }

        // misc tails (scalar; ~2.5M elements total)
        const unsigned szA = G2 * 9u;
        const unsigned szB = G2 * 3u;
        const unsigned szC = 2u * G2;
        const unsigned szD = KB;
        const unsigned szE_ = KB;
        const unsigned szF = KB * 9u;
        const unsigned szG = KB * 3u;
        const unsigned szH = KB * 76u;
        const unsigned TOT = szA + szB + szC + szD + szE_ + szF + szG + szH;

        const unsigned bTTSROT = (unsigned)OFF_TTSROT + (unsigned)E * 9u;
        const unsigned bTTSTR  = (unsigned)OFF_TTSTRANS + (unsigned)E * 3u;
        const unsigned bEIDX   = (unsigned)OFF_EIDX;
        const unsigned bBATCH  = (unsigned)OFF_BATCH + (unsigned)N;
        const unsigned bCHAIN  = (unsigned)OFF_CHAIN + (unsigned)N;
        const unsigned bTROT   = (unsigned)OFF_TROT + (unsigned)N * 9u;
        const unsigned bTTRANS = (unsigned)OFF_TTRANS + (unsigned)N * 3u;
        const unsigned bV      = (unsigned)OFF_V + (unsigned)N * 76u;
        const unsigned uN = (unsigned)N, uE = (unsigned)E;

        unsigned stride = (unsigned)NFB * 128u;
        for (unsigned j0 = fb * 128u + tid; j0 < TOT; j0 += stride) {
            unsigned j = j0;
            unsigned idx; float v;
            if (j < szA) {
                unsigned c = j % 9u;
                idx = bTTSROT + j; v = (c == 0u || c == 4u || c == 8u) ? 1.f : 0.f;
            } else if ((j -= szA) < szB) {
                idx = bTTSTR + j; v = 0.f;
            } else if ((j -= szB) < szC) {
                if (j < G2) {
                    v = (j < KN) ? (float)(uN + (unsigned)batch_id[j % uN] + (j / uN) * NB)
                                 : (float)((j - KN) % uN);
                    idx = bEIDX + uE + j;
                } else {
                    unsigned t = j - G2;
                    v = (t < KN) ? (float)(t % uN)
                                 : (float)(uN + (unsigned)batch_id[(t - KN) % uN] + ((t - KN) / uN) * NB);
                    idx = bEIDX + uET + uE + t;
                }
            } else if ((j -= szC) < szD) {
                idx = bBATCH + j; v = (float)(j % NB);
            } else if ((j -= szD) < szE_) {
                idx = bCHAIN + j; v = 1001.f;
            } else if ((j -= szE_) < szF) {
                unsigned c = j % 9u;
                idx = bTROT + j; v = (c == 0u || c == 4u || c == 8u) ? 1.f : 0.f;
            } else if ((j -= szF) < szG) {
                idx = bTTRANS + j; v = 0.f;
            } else {
                j -= szG;
                unsigned r = j / 76u, c = j % 76u;
                unsigned k = r / NB;
                unsigned m = (c < 38u) ? c : c - 38u;
                double f = exp(-(double)(2u * m) * 9.210340371976184 / 76.0);
                double ang = (double)k * f;
                idx = bV + j; v = (float)((c < 38u) ? cos(ang) : sin(ang));
            }
            out[idx] = v;
        }

        if (tid == 0) tma_wait_read0();
    }
}

// ---------------------------------------------------------------------------
extern "C" void kernel_launch(void* const* d_in, const int* in_sizes, int n_in,
                              void* d_out, int out_size) {
    const float* X        = (const float*)d_in[0];
    const int*   node_idx = (const int*)d_in[1];
    const int*   eix      = (const int*)d_in[2];
    const int*   batch_id = (const int*)d_in[3];
    const int*   chain    = (const int*)d_in[4];
    float* out = (float*)d_out;

    int N = in_sizes[0] / 12;
    int E = in_sizes[2] / 2;
    int NT = N + KF * NB;
    int G2 = 2 * KF * N;
    int ET = E + G2;

    long long OFF_V        = 0;
    long long OFF_E        = OFF_V + (long long)NT * 76;
    long long OFF_TROT     = OFF_E + (long long)ET * EW;
    long long OFF_TTRANS   = OFF_TROT + (long long)NT * 9;
    long long OFF_TTSROT   = OFF_TTRANS + (long long)NT * 3;
    long long OFF_TTSTRANS = OFF_TTSROT + (long long)ET * 9;
    long long OFF_BATCH    = OFF_TTSTRANS + (long long)ET * 3;
    long long OFF_EIDX     = OFF_BATCH + NT;
    long long OFF_CHAIN    = OFF_EIDX + 2LL * ET;

    int nEB = (E + TILE - 1) / TILE;   // E divisible by TILE
    int nNB = (N + NTILE - 1) / NTILE;
    int grid = NFB + nNB + nEB;
    int smem = SM_TOTAL * (int)sizeof(float);   // 28800 B

    static bool attr_done = false;
    if (!attr_done) {
        cudaFuncSetAttribute(fused_kernel, cudaFuncAttributeMaxDynamicSharedMemorySize, smem);
        attr_done = true;
    }

    fused_kernel<<<grid, 128, smem>>>(X, node_idx, eix, batch_id, chain, out,
                                      N, E, nEB, nNB,
                                      OFF_V, OFF_E, OFF_TROT, OFF_TTRANS,
                                      OFF_TTSROT, OFF_TTSTRANS,
                                      OFF_BATCH, OFF_EIDX, OFF_CHAIN);
}

// round 15
// speedup vs baseline: 1.4502x; 1.0137x over previous
#include <cuda_runtime.h>
#include <math.h>
#include <stdint.h>

// GeoFeaturizer for GB300 (sm_103a). B=8 batches, K=3 virtual frames (fixed).
#define NB 8
#define KF 3
#define TILE 24        // edges per edge-block (4 threads per edge, blockDim=128)
#define NTILE 48       // nodes per node-block
#define EW 213         // edge feature width
#define NFB 888        // fill/misc blocks (scheduled FIRST)

// pos-embedding freqs: 10000^(-j/8) = 10^(-j/2)
__constant__ float c_posfreq[8] = {
    1.0f, 0.31622776601683794f, 0.1f, 0.031622776601683794f,
    0.01f, 0.0031622776601683794f, 0.001f, 0.00031622776601683794f
};

// ---- TMA bulk-store helpers (smem -> gmem, L1-bypassing) ----
__device__ __forceinline__ void tma_bulk_store(void* gptr, uint32_t saddr, uint32_t bytes) {
    asm volatile("cp.async.bulk.global.shared::cta.bulk_group [%0], [%1], %2;"
                 :: "l"(gptr), "r"(saddr), "r"(bytes) : "memory");
}
__device__ __forceinline__ void tma_fence() {
    asm volatile("fence.proxy.async.shared::cta;" ::: "memory");
}
__device__ __forceinline__ void tma_commit() {
    asm volatile("cp.async.bulk.commit_group;" ::: "memory");
}
__device__ __forceinline__ void tma_wait_read0() {
    asm volatile("cp.async.bulk.wait_group.read 0;" ::: "memory");
}

__device__ __forceinline__ float ex2(float x) {
    float r;
    asm("ex2.approx.ftz.f32 %0, %1;" : "=f"(r) : "f"(x));
    return r;
}

// decouple(): 3 direction comps + 16 RBF. RBF via exp2: exp(-u^2)=2^(-(u*sqrt(log2 e))^2).
// a2 = 0.8*sqrt(log2e)*norm steps by c2 = (16/15)*sqrt(log2e).
__device__ __forceinline__ void dec3(float* __restrict__ w, float x, float y, float z) {
    float sq   = x*x + y*y + z*z;
    float norm = sqrtf(sq + 1e-12f);
    float inv  = (norm < 1e-4f) ? 0.f : __fdividef(1.f, norm + 1e-6f);
    w[0] = x * inv; w[1] = y * inv; w[2] = z * inv;
    float a2 = 0.96089792702916f * norm;          // 0.8*sqrt(log2 e)
#pragma unroll
    for (int r = 0; r < 16; r++) {
        float u = a2 - (float)r * 1.2811972360389f;  // (16/15)*sqrt(log2 e)
        w[3 + r] = ex2(-u * u);
    }
}

// f32 Cody-Waite reduction then fast sin/cos (|ang| <= ~3.2e4).
__device__ __forceinline__ void fast_sincos(float ang, float* s, float* c) {
    const float INV2PI = 0.15915494309189535f;
    const float PI2_HI = 6.28318548202514648f;
    const float PI2_LO = -1.74845553146357e-07f;
    float k = rintf(ang * INV2PI);
    float r = fmaf(-k, PI2_HI, ang);
    r = fmaf(-k, PI2_LO, r);
    *s = __sinf(r);
    *c = __cosf(r);
}

// Frame from atoms 0,1,2 (N, CA, C). R is the reference's stored R (= M^T).
__device__ __forceinline__ void make_frame(const float a0[3], const float a1[3], const float a2v[3],
                                           float R[3][3]) {
    float nx = a0[0] - a1[0], ny_ = a0[1] - a1[1], nz_ = a0[2] - a1[2];
    float cx = a2v[0] - a1[0], cy  = a2v[1] - a1[1], cz  = a2v[2] - a1[2];
    const float EPSf = 1e-20f;
    float nrm  = sqrtf(EPSf + cx*cx + cy*cy);
    float s1 = -cy / nrm, c1 = cx / nrm;
    float nrm2 = sqrtf(EPSf + cx*cx + cy*cy + cz*cz);
    float s2 = cz / nrm2;
    float c2 = sqrtf(cx*cx + cy*cy) / nrm2;
    float Rc[3][3] = {
        { c2*c1, -c2*s1, s2 },
        { s1,     c1,    0.f},
        {-s2*c1,  s2*s1, c2 }
    };
    float nr1 = Rc[1][0]*nx + Rc[1][1]*ny_;
    float nr2 = Rc[2][0]*nx + Rc[2][1]*ny_ + Rc[2][2]*nz_;
    float nrm3 = sqrtf(EPSf + nr1*nr1 + nr2*nr2);
    float sn = -nr2 / nrm3, cn = nr1 / nrm3;
    float M1[3], M2[3];
#pragma unroll
    for (int j = 0; j < 3; j++) {
        M1[j] = cn * Rc[1][j] - sn * Rc[2][j];
        M2[j] = sn * Rc[1][j] + cn * Rc[2][j];
    }
#pragma unroll
    for (int j = 0; j < 3; j++) {
        R[j][0] = Rc[0][j];
        R[j][1] = M1[j];
        R[j][2] = M2[j];
    }
}

// edge smem layout (floats): [0, TILE*EW) rows; TILE*9 rot; TILE*3 trans
#define SM_ROT   (TILE * EW)                // 5112
#define SM_TRANS (SM_ROT + TILE * 9)        // 5328
#define SM_TOTAL (SM_TRANS + TILE * 3)      // 5400 floats = 21600 B

// node smem layout (floats)
#define SV_V     0
#define SV_TROT  (NTILE * 76)               // 3648
#define SV_TTR   (SV_TROT + NTILE * 9)      // 4080
#define SV_B     (SV_TTR + NTILE * 3)       // 4224
#define SV_C     (SV_B + NTILE)             // 4272 (end 4320)

// ---------------------------------------------------------------------------
// Role order by bid: [0,NFB) fill+misc | [NFB,NFB+nNB) node | rest edge.
// ---------------------------------------------------------------------------
__global__ void __launch_bounds__(128, 9)
fused_kernel(const float* __restrict__ X,
             const int*  __restrict__ node_idx,
             const int*  __restrict__ eix,       // (2, E) row-major
             const int*  __restrict__ batch_id,
             const int*  __restrict__ chain,
             float* __restrict__ out,
             int N, int E, int nEB, int nNB,
             long long OFF_V, long long OFF_E, long long OFF_TROT,
             long long OFF_TTRANS, long long OFF_TTSROT, long long OFF_TTSTRANS,
             long long OFF_BATCH, long long OFF_EIDX, long long OFF_CHAIN) {
    extern __shared__ float sm[];
    int tid = threadIdx.x;
    int bid = blockIdx.x;
    const int ET = E + 2 * KF * N;
    uint32_t smBase = (uint32_t)__cvta_generic_to_shared(sm);

    if (bid >= NFB + nNB) {
        // ------------------------------------------------ edge role (E % TILE == 0)
        int eSlot = tid >> 2;          // 0..31 (only 0..TILE-1 active)
        int sub   = tid & 3;           // 0..3
        int e0 = (bid - NFB - nNB) * TILE;
        int e  = e0 + eSlot;
        bool active = (eSlot < TILE);

        if (active) {
            float* w = sm + eSlot * EW;
            int s = min(max(eix[e], 0), N - 1);
            int d = min(max(eix[E + e], 0), N - 1);

            const float4* Xs4 = reinterpret_cast<const float4*>(X) + (size_t)s * 3;
            const float4* Xd4 = reinterpret_cast<const float4*>(X) + (size_t)d * 3;
            float4 sa = Xs4[0], sb = Xs4[1], sc = Xs4[2];
            float4 da = Xd4[0], db = Xd4[1], dc = Xd4[2];
            float P[8][3] = {
                {sa.x, sa.y, sa.z}, {sa.w, sb.x, sb.y}, {sb.z, sb.w, sc.x}, {sc.y, sc.z, sc.w},
                {da.x, da.y, da.z}, {da.w, db.x, db.y}, {db.z, db.w, dc.x}, {dc.y, dc.z, dc.w}
            };

            float Rs[3][3];
            make_frame(P[0], P[1], P[2], Rs);
            float ts[3] = {P[1][0], P[1][1], P[1][2]};

            // each sub: 2 of the 8 atom dec3s (cols 0..151)
#pragma unroll
            for (int k = 0; k < 2; k++) {
                int a8 = 2 * sub + k;
                float q0 = P[a8][0] - ts[0], q1 = P[a8][1] - ts[1], q2 = P[a8][2] - ts[2];
                float l0 = Rs[0][0]*q0 + Rs[1][0]*q1 + Rs[2][0]*q2;
                float l1 = Rs[0][1]*q0 + Rs[1][1]*q1 + Rs[2][1]*q2;
                float l2 = Rs[0][2]*q0 + Rs[1][2]*q1 + Rs[2][2]*q2;
                dec3(w + a8 * 19, l0, l1, l2);
            }

            if (sub == 0) {
                // Q = Rs^T Rd; E_quant (cols 152..160) = Q; Tts_rot staging = Q^T
                float Rd[3][3];
                make_frame(P[4], P[5], P[6], Rd);
                float Q[3][3];
#pragma unroll
                for (int i = 0; i < 3; i++)
#pragma unroll
                    for (int j = 0; j < 3; j++)
                        Q[i][j] = Rs[0][i]*Rd[0][j] + Rs[1][i]*Rd[1][j] + Rs[2][i]*Rd[2][j];
#pragma unroll
                for (int i = 0; i < 3; i++)
#pragma unroll
                    for (int j = 0; j < 3; j++) {
                        w[152 + 3 * i + j] = Q[i][j];
                        sm[SM_ROT + eSlot * 9 + 3 * j + i] = Q[i][j];
                    }
            } else if (sub == 1) {
                // tts = Rd^T (t_src - t_dst); E_trans (cols 161..179)
                float Rd[3][3];
                make_frame(P[4], P[5], P[6], Rd);
                float dt0 = ts[0] - P[5][0], dt1 = ts[1] - P[5][1], dt2 = ts[2] - P[5][2];
                float t0 = Rd[0][0]*dt0 + Rd[1][0]*dt1 + Rd[2][0]*dt2;
                float t1 = Rd[0][1]*dt0 + Rd[1][1]*dt1 + Rd[2][1]*dt2;
                float t2 = Rd[0][2]*dt0 + Rd[1][2]*dt1 + Rd[2][2]*dt2;
                dec3(w + 161, t0, t1, t2);
                sm[SM_TRANS + eSlot * 3 + 0] = t0;
                sm[SM_TRANS + eSlot * 3 + 1] = t1;
                sm[SM_TRANS + eSlot * 3 + 2] = t2;
            } else if (sub == 2) {
                // pos embedding (cols 180..195)
                float dd = (float)(s - d);
#pragma unroll
                for (int j = 0; j < 8; j++) {
                    float ang = __fmul_rn(dd, c_posfreq[j]);
                    float si, co;
                    fast_sincos(ang, &si, &co);
                    w[180 + j] = co;
                    w[188 + j] = si;
                }
            } else {
                // E_bias (cols 196..212) + eidx outputs
                float bb = (float)(node_idx[s] - node_idx[d]);
                float nb = sqrtf(bb * bb + 1e-12f);
                float ib = (nb < 1e-4f) ? 0.f : __fdividef(1.f, nb + 1e-6f);
                w[196] = bb * ib;
                float ab = 0.96089792702916f * nb;
#pragma unroll
                for (int r = 0; r < 16; r++) {
                    float u = ab - (float)r * 1.2811972360389f;
                    w[197 + r] = ex2(-u * u);
                }
                out[OFF_EIDX + e]      = (float)eix[e];
                out[OFF_EIDX + ET + e] = (float)eix[E + e];
            }
        }
        __syncthreads();

        if (tid == 0) {
            tma_fence();
            tma_bulk_store(out + OFF_E + (long long)e0 * EW,       smBase,                  TILE * EW * 4u);
            tma_bulk_store(out + OFF_TTSROT + (long long)e0 * 9,   smBase + SM_ROT * 4u,    TILE * 9 * 4u);
            tma_bulk_store(out + OFF_TTSTRANS + (long long)e0 * 3, smBase + SM_TRANS * 4u,  TILE * 3 * 4u);
            tma_commit();
            tma_wait_read0();
        }
    } else if (bid >= NFB) {
        // ------------------------------------------------ node role (48 nodes/block)
        int n0 = (bid - NFB) * NTILE;
        int n  = n0 + tid;
        int rem = min(NTILE, N - n0);   // always 48 (N % NTILE == 0)

        if (tid < NTILE && n < N) {
            const float4* X4 = reinterpret_cast<const float4*>(X) + (size_t)n * 3;
            float4 xa = X4[0], xb = X4[1], xc = X4[2];
            float ax[4][3] = {
                {xa.x, xa.y, xa.z}, {xa.w, xb.x, xb.y},
                {xb.z, xb.w, xc.x}, {xc.y, xc.z, xc.w}
            };
            float R[3][3];
            make_frame(ax[0], ax[1], ax[2], R);

#pragma unroll
            for (int i = 0; i < 3; i++)
#pragma unroll
                for (int j = 0; j < 3; j++)
                    sm[SV_TROT + tid * 9 + 3 * i + j] = R[i][j];
            sm[SV_TTR + tid * 3 + 0] = ax[1][0];
            sm[SV_TTR + tid * 3 + 1] = ax[1][1];
            sm[SV_TTR + tid * 3 + 2] = ax[1][2];
            sm[SV_B + tid] = (float)batch_id[n];
            sm[SV_C + tid] = (float)chain[n];

            bool start = (n == 0) || (batch_id[n] != batch_id[n - 1]);
            float prev0 = 0.f, prev1 = 0.f, prev2 = 0.f;
            if (n > 0) {
                const float* xp = X + (size_t)(n - 1) * 12 + 9;
                prev0 = xp[0]; prev1 = xp[1]; prev2 = xp[2];
            }
            float* wv = sm + SV_V + tid * 76;
#pragma unroll
            for (int a = 0; a < 4; a++) {
                float dx, dy, dz;
                if (start) { dx = dy = dz = 0.f; }
                else {
                    float px, py, pz;
                    if (a == 0) { px = prev0; py = prev1; pz = prev2; }
                    else        { px = ax[a-1][0]; py = ax[a-1][1]; pz = ax[a-1][2]; }
                    dx = ax[a][0] - px; dy = ax[a][1] - py; dz = ax[a][2] - pz;
                }
                float l0 = R[0][0]*dx + R[1][0]*dy + R[2][0]*dz;
                float l1 = R[0][1]*dx + R[1][1]*dy + R[2][1]*dz;
                float l2 = R[0][2]*dx + R[1][2]*dy + R[2][2]*dz;
                dec3(wv + a * 19, l0, l1, l2);
            }
        }
        __syncthreads();

        if (tid == 0 && rem > 0) {
            tma_fence();
            tma_bulk_store(out + OFF_V + (long long)n0 * 76,     smBase + SV_V * 4u,    (uint32_t)(rem * 76 * 4));
            tma_bulk_store(out + OFF_TROT + (long long)n0 * 9,   smBase + SV_TROT * 4u, (uint32_t)(rem * 9 * 4));
            tma_bulk_store(out + OFF_TTRANS + (long long)n0 * 3, smBase + SV_TTR * 4u,  (uint32_t)(rem * 3 * 4));
            tma_bulk_store(out + OFF_BATCH + n0,                 smBase + SV_B * 4u,    (uint32_t)(rem * 4));
            tma_bulk_store(out + OFF_CHAIN + n0,                 smBase + SV_C * 4u,    (uint32_t)(rem * 4));
            tma_commit();
            tma_wait_read0();
        }
    } else {
        // ------------------------------------------------ fill + misc role (FIRST)
        const unsigned KN = KF * (unsigned)N, G2 = 2u * KN, uET = (unsigned)E + G2, KB = KF * NB;
        const unsigned zelems = G2 * (unsigned)EW;               // zero-region floats
        const unsigned CHUNKF = TILE * EW;                       // 5112 floats = 20448 B
        const unsigned nChunk = zelems / CHUNKF;
        const unsigned tailF  = zelems - nChunk * CHUNKF;        // 0 for these shapes
        const long long zbase = OFF_E + (long long)E * EW;

        unsigned fb = (unsigned)bid;

        for (int i = tid; i < (int)CHUNKF; i += 128) sm[i] = 0.f;
        __syncthreads();

        if (tid == 0) {
            tma_fence();
            for (unsigned c = fb; c < nChunk; c += NFB)
                tma_bulk_store(out + zbase + (long long)c * CHUNKF, smBase, CHUNKF * 4u);
            if (fb == 0 && tailF)
                tma_bulk_store(out + zbase + (long long)nChunk * CHUNKF, smBase, tailF * 4u);
            tma_commit();
        }

        // misc tails (scalar; ~2.5M elements total)
        const unsigned szA = G2 * 9u;
        const unsigned szB = G2 * 3u;
        const unsigned szC = 2u * G2;
        const unsigned szD = KB;
        const unsigned szE_ = KB;
        const unsigned szF = KB * 9u;
        const unsigned szG = KB * 3u;
        const unsigned szH = KB * 76u;
        const unsigned TOT = szA + szB + szC + szD + szE_ + szF + szG + szH;

        const unsigned bTTSROT = (unsigned)OFF_TTSROT + (unsigned)E * 9u;
        const unsigned bTTSTR  = (unsigned)OFF_TTSTRANS + (unsigned)E * 3u;
        const unsigned bEIDX   = (unsigned)OFF_EIDX;
        const unsigned bBATCH  = (unsigned)OFF_BATCH + (unsigned)N;
        const unsigned bCHAIN  = (unsigned)OFF_CHAIN + (unsigned)N;
        const unsigned bTROT   = (unsigned)OFF_TROT + (unsigned)N * 9u;
        const unsigned bTTRANS = (unsigned)OFF_TTRANS + (unsigned)N * 3u;
        const unsigned bV      = (unsigned)OFF_V + (unsigned)N * 76u;
        const unsigned uN = (unsigned)N, uE = (unsigned)E;

        unsigned stride = (unsigned)NFB * 128u;
        for (unsigned j0 = fb * 128u + tid; j0 < TOT; j0 += stride) {
            unsigned j = j0;
            unsigned idx; float v;
            if (j < szA) {
                unsigned c = j % 9u;
                idx = bTTSROT + j; v = (c == 0u || c == 4u || c == 8u) ? 1.f : 0.f;
            } else if ((j -= szA) < szB) {
                idx = bTTSTR + j; v = 0.f;
            } else if ((j -= szB) < szC) {
                if (j < G2) {
                    v = (j < KN) ? (float)(uN + (unsigned)batch_id[j % uN] + (j / uN) * NB)
                                 : (float)((j - KN) % uN);
                    idx = bEIDX + uE + j;
                } else {
                    unsigned t = j - G2;
                    v = (t < KN) ? (float)(t % uN)
                                 : (float)(uN + (unsigned)batch_id[(t - KN) % uN] + ((t - KN) / uN) * NB);
                    idx = bEIDX + uET + uE + t;
                }
            } else if ((j -= szC) < szD) {
                idx = bBATCH + j; v = (float)(j % NB);
            } else if ((j -= szD) < szE_) {
                idx = bCHAIN + j; v = 1001.f;
            } else if ((j -= szE_) < szF) {
                unsigned c = j % 9u;
                idx = bTROT + j; v = (c == 0u || c == 4u || c == 8u) ? 1.f : 0.f;
            } else if ((j -= szF) < szG) {
                idx = bTTRANS + j; v = 0.f;
            } else {
                j -= szG;
                unsigned r = j / 76u, c = j % 76u;
                unsigned k = r / NB;
                unsigned m = (c < 38u) ? c : c - 38u;
                double f = exp(-(double)(2u * m) * 9.210340371976184 / 76.0);
                double ang = (double)k * f;
                idx = bV + j; v = (float)((c < 38u) ? cos(ang) : sin(ang));
            }
            out[idx] = v;
        }

        if (tid == 0) tma_wait_read0();
    }
}

// ---------------------------------------------------------------------------
extern "C" void kernel_launch(void* const* d_in, const int* in_sizes, int n_in,
                              void* d_out, int out_size) {
    const float* X        = (const float*)d_in[0];
    const int*   node_idx = (const int*)d_in[1];
    const int*   eix      = (const int*)d_in[2];
    const int*   batch_id = (const int*)d_in[3];
    const int*   chain    = (const int*)d_in[4];
    float* out = (float*)d_out;

    int N = in_sizes[0] / 12;
    int E = in_sizes[2] / 2;
    int NT = N + KF * NB;
    int G2 = 2 * KF * N;
    int ET = E + G2;

    long long OFF_V        = 0;
    long long OFF_E        = OFF_V + (long long)NT * 76;
    long long OFF_TROT     = OFF_E + (long long)ET * EW;
    long long OFF_TTRANS   = OFF_TROT + (long long)NT * 9;
    long long OFF_TTSROT   = OFF_TTRANS + (long long)NT * 3;
    long long OFF_TTSTRANS = OFF_TTSROT + (long long)ET * 9;
    long long OFF_BATCH    = OFF_TTSTRANS + (long long)ET * 3;
    long long OFF_EIDX     = OFF_BATCH + NT;
    long long OFF_CHAIN    = OFF_EIDX + 2LL * ET;

    int nEB = (E + TILE - 1) / TILE;   // 600000/24 = 25000
    int nNB = (N + NTILE - 1) / NTILE; // 30000/48 = 625
    int grid = NFB + nNB + nEB;
    int smem = SM_TOTAL * (int)sizeof(float);   // 21600 B

    static bool attr_done = false;
    if (!attr_done) {
        cudaFuncSetAttribute(fused_kernel, cudaFuncAttributeMaxDynamicSharedMemorySize, smem);
        attr_done = true;
    }

    fused_kernel<<<grid, 128, smem>>>(X, node_idx, eix, batch_id, chain, out,
                                      N, E, nEB, nNB,
                                      OFF_V, OFF_E, OFF_TROT, OFF_TTRANS,
                                      OFF_TTSROT, OFF_TTSTRANS,
                                      OFF_BATCH, OFF_EIDX, OFF_CHAIN);
}

// round 16
// speedup vs baseline: 1.5211x; 1.0489x over previous
#include <cuda_runtime.h>
#include <math.h>
#include <stdint.h>

// GeoFeaturizer for GB300 (sm_103a). B=8 batches, K=3 virtual frames (fixed).
#define NB 8
#define KF 3
#define TILE 24        // edges per edge-block (4 threads per edge, blockDim=96: all active)
#define NTILE 48       // nodes per node-block
#define EW 213         // edge feature width
#define NFB 888        // fill/misc blocks (scheduled FIRST)
#define BLK 96

// pos-embedding freqs: 10000^(-j/8) = 10^(-j/2)
__constant__ float c_posfreq[8] = {
    1.0f, 0.31622776601683794f, 0.1f, 0.031622776601683794f,
    0.01f, 0.0031622776601683794f, 0.001f, 0.00031622776601683794f
};

// ---- TMA bulk-store helpers (smem -> gmem, L1-bypassing) ----
__device__ __forceinline__ void tma_bulk_store(void* gptr, uint32_t saddr, uint32_t bytes) {
    asm volatile("cp.async.bulk.global.shared::cta.bulk_group [%0], [%1], %2;"
                 :: "l"(gptr), "r"(saddr), "r"(bytes) : "memory");
}
__device__ __forceinline__ void tma_fence() {
    asm volatile("fence.proxy.async.shared::cta;" ::: "memory");
}
__device__ __forceinline__ void tma_commit() {
    asm volatile("cp.async.bulk.commit_group;" ::: "memory");
}
__device__ __forceinline__ void tma_wait_read0() {
    asm volatile("cp.async.bulk.wait_group.read 0;" ::: "memory");
}

__device__ __forceinline__ float ex2(float x) {
    float r;
    asm("ex2.approx.ftz.f32 %0, %1;" : "=f"(r) : "f"(x));
    return r;
}

// decouple(): 3 direction comps + 16 RBF. RBF via exp2: exp(-u^2)=2^(-(u*sqrt(log2 e))^2).
__device__ __forceinline__ void dec3(float* __restrict__ w, float x, float y, float z) {
    float sq   = x*x + y*y + z*z;
    float norm = sqrtf(sq + 1e-12f);
    float inv  = (norm < 1e-4f) ? 0.f : __fdividef(1.f, norm + 1e-6f);
    w[0] = x * inv; w[1] = y * inv; w[2] = z * inv;
    float a2 = 0.96089792702916f * norm;          // 0.8*sqrt(log2 e)
#pragma unroll
    for (int r = 0; r < 16; r++) {
        float u = a2 - (float)r * 1.2811972360389f;  // (16/15)*sqrt(log2 e)
        w[3 + r] = ex2(-u * u);
    }
}

// f32 Cody-Waite reduction then fast sin/cos (|ang| <= ~3.2e4).
__device__ __forceinline__ void fast_sincos(float ang, float* s, float* c) {
    const float INV2PI = 0.15915494309189535f;
    const float PI2_HI = 6.28318548202514648f;
    const float PI2_LO = -1.74845553146357e-07f;
    float k = rintf(ang * INV2PI);
    float r = fmaf(-k, PI2_HI, ang);
    r = fmaf(-k, PI2_LO, r);
    *s = __sinf(r);
    *c = __cosf(r);
}

// Frame from atoms 0,1,2 (N, CA, C). R is the reference's stored R (= M^T).
__device__ __forceinline__ void make_frame(const float a0[3], const float a1[3], const float a2v[3],
                                           float R[3][3]) {
    float nx = a0[0] - a1[0], ny_ = a0[1] - a1[1], nz_ = a0[2] - a1[2];
    float cx = a2v[0] - a1[0], cy  = a2v[1] - a1[1], cz  = a2v[2] - a1[2];
    const float EPSf = 1e-20f;
    float nrm  = sqrtf(EPSf + cx*cx + cy*cy);
    float s1 = -cy / nrm, c1 = cx / nrm;
    float nrm2 = sqrtf(EPSf + cx*cx + cy*cy + cz*cz);
    float s2 = cz / nrm2;
    float c2 = sqrtf(cx*cx + cy*cy) / nrm2;
    float Rc[3][3] = {
        { c2*c1, -c2*s1, s2 },
        { s1,     c1,    0.f},
        {-s2*c1,  s2*s1, c2 }
    };
    float nr1 = Rc[1][0]*nx + Rc[1][1]*ny_;
    float nr2 = Rc[2][0]*nx + Rc[2][1]*ny_ + Rc[2][2]*nz_;
    float nrm3 = sqrtf(EPSf + nr1*nr1 + nr2*nr2);
    float sn = -nr2 / nrm3, cn = nr1 / nrm3;
    float M1[3], M2[3];
#pragma unroll
    for (int j = 0; j < 3; j++) {
        M1[j] = cn * Rc[1][j] - sn * Rc[2][j];
        M2[j] = sn * Rc[1][j] + cn * Rc[2][j];
    }
#pragma unroll
    for (int j = 0; j < 3; j++) {
        R[j][0] = Rc[0][j];
        R[j][1] = M1[j];
        R[j][2] = M2[j];
    }
}

// edge smem layout (floats): [0, TILE*EW) rows; TILE*9 rot; TILE*3 trans
#define SM_ROT   (TILE * EW)                // 5112
#define SM_TRANS (SM_ROT + TILE * 9)        // 5328
#define SM_TOTAL (SM_TRANS + TILE * 3)      // 5400 floats = 21600 B

// node smem layout (floats)
#define SV_V     0
#define SV_TROT  (NTILE * 76)               // 3648
#define SV_TTR   (SV_TROT + NTILE * 9)      // 4080
#define SV_B     (SV_TTR + NTILE * 3)       // 4224
#define SV_C     (SV_B + NTILE)             // 4272 (end 4320)

// ---------------------------------------------------------------------------
// Role order by bid: [0,NFB) fill+misc | [NFB,NFB+nNB) node | rest edge.
// ---------------------------------------------------------------------------
__global__ void __launch_bounds__(BLK, 10)
fused_kernel(const float* __restrict__ X,
             const int*  __restrict__ node_idx,
             const int*  __restrict__ eix,       // (2, E) row-major
             const int*  __restrict__ batch_id,
             const int*  __restrict__ chain,
             float* __restrict__ out,
             int N, int E, int nEB, int nNB,
             long long OFF_V, long long OFF_E, long long OFF_TROT,
             long long OFF_TTRANS, long long OFF_TTSROT, long long OFF_TTSTRANS,
             long long OFF_BATCH, long long OFF_EIDX, long long OFF_CHAIN) {
    extern __shared__ float sm[];
    int tid = threadIdx.x;
    int bid = blockIdx.x;
    const int ET = E + 2 * KF * N;
    uint32_t smBase = (uint32_t)__cvta_generic_to_shared(sm);

    if (bid >= NFB + nNB) {
        // ------------------------------------------------ edge role (E % TILE == 0)
        int eSlot = tid >> 2;          // 0..23 (all active with BLK=96)
        int sub   = tid & 3;           // 0..3
        int e0 = (bid - NFB - nNB) * TILE;
        int e  = e0 + eSlot;

        {
            float* w = sm + eSlot * EW;
            int s = min(max(eix[e], 0), N - 1);
            int d = min(max(eix[E + e], 0), N - 1);

            const float4* Xs4 = reinterpret_cast<const float4*>(X) + (size_t)s * 3;
            const float4* Xd4 = reinterpret_cast<const float4*>(X) + (size_t)d * 3;
            float4 sa = Xs4[0], sb = Xs4[1], sc = Xs4[2];
            float4 da = Xd4[0], db = Xd4[1], dc = Xd4[2];
            float P[8][3] = {
                {sa.x, sa.y, sa.z}, {sa.w, sb.x, sb.y}, {sb.z, sb.w, sc.x}, {sc.y, sc.z, sc.w},
                {da.x, da.y, da.z}, {da.w, db.x, db.y}, {db.z, db.w, dc.x}, {dc.y, dc.z, dc.w}
            };

            float Rs[3][3];
            make_frame(P[0], P[1], P[2], Rs);
            float ts[3] = {P[1][0], P[1][1], P[1][2]};

            // each sub: 2 of the 8 atom dec3s (cols 0..151)
#pragma unroll
            for (int k = 0; k < 2; k++) {
                int a8 = 2 * sub + k;
                float q0 = P[a8][0] - ts[0], q1 = P[a8][1] - ts[1], q2 = P[a8][2] - ts[2];
                float l0 = Rs[0][0]*q0 + Rs[1][0]*q1 + Rs[2][0]*q2;
                float l1 = Rs[0][1]*q0 + Rs[1][1]*q1 + Rs[2][1]*q2;
                float l2 = Rs[0][2]*q0 + Rs[1][2]*q1 + Rs[2][2]*q2;
                dec3(w + a8 * 19, l0, l1, l2);
            }

            if (sub == 0) {
                // Q = Rs^T Rd; E_quant (cols 152..160) = Q; Tts_rot staging = Q^T
                float Rd[3][3];
                make_frame(P[4], P[5], P[6], Rd);
                float Q[3][3];
#pragma unroll
                for (int i = 0; i < 3; i++)
#pragma unroll
                    for (int j = 0; j < 3; j++)
                        Q[i][j] = Rs[0][i]*Rd[0][j] + Rs[1][i]*Rd[1][j] + Rs[2][i]*Rd[2][j];
#pragma unroll
                for (int i = 0; i < 3; i++)
#pragma unroll
                    for (int j = 0; j < 3; j++) {
                        w[152 + 3 * i + j] = Q[i][j];
                        sm[SM_ROT + eSlot * 9 + 3 * j + i] = Q[i][j];
                    }
            } else if (sub == 1) {
                // tts = Rd^T (t_src - t_dst); E_trans (cols 161..179)
                float Rd[3][3];
                make_frame(P[4], P[5], P[6], Rd);
                float dt0 = ts[0] - P[5][0], dt1 = ts[1] - P[5][1], dt2 = ts[2] - P[5][2];
                float t0 = Rd[0][0]*dt0 + Rd[1][0]*dt1 + Rd[2][0]*dt2;
                float t1 = Rd[0][1]*dt0 + Rd[1][1]*dt1 + Rd[2][1]*dt2;
                float t2 = Rd[0][2]*dt0 + Rd[1][2]*dt1 + Rd[2][2]*dt2;
                dec3(w + 161, t0, t1, t2);
                sm[SM_TRANS + eSlot * 3 + 0] = t0;
                sm[SM_TRANS + eSlot * 3 + 1] = t1;
                sm[SM_TRANS + eSlot * 3 + 2] = t2;
            } else if (sub == 2) {
                // pos embedding (cols 180..195)
                float dd = (float)(s - d);
#pragma unroll
                for (int j = 0; j < 8; j++) {
                    float ang = __fmul_rn(dd, c_posfreq[j]);
                    float si, co;
                    fast_sincos(ang, &si, &co);
                    w[180 + j] = co;
                    w[188 + j] = si;
                }
            } else {
                // E_bias (cols 196..212) + eidx outputs
                float bb = (float)(node_idx[s] - node_idx[d]);
                float nb = sqrtf(bb * bb + 1e-12f);
                float ib = (nb < 1e-4f) ? 0.f : __fdividef(1.f, nb + 1e-6f);
                w[196] = bb * ib;
                float ab = 0.96089792702916f * nb;
#pragma unroll
                for (int r = 0; r < 16; r++) {
                    float u = ab - (float)r * 1.2811972360389f;
                    w[197 + r] = ex2(-u * u);
                }
                out[OFF_EIDX + e]      = (float)eix[e];
                out[OFF_EIDX + ET + e] = (float)eix[E + e];
            }
        }
        __syncthreads();

        if (tid == 0) {
            tma_fence();
            tma_bulk_store(out + OFF_E + (long long)e0 * EW,       smBase,                  TILE * EW * 4u);
            tma_bulk_store(out + OFF_TTSROT + (long long)e0 * 9,   smBase + SM_ROT * 4u,    TILE * 9 * 4u);
            tma_bulk_store(out + OFF_TTSTRANS + (long long)e0 * 3, smBase + SM_TRANS * 4u,  TILE * 3 * 4u);
            tma_commit();
            tma_wait_read0();
        }
    } else if (bid >= NFB) {
        // ------------------------------------------------ node role (48 nodes/block)
        int n0 = (bid - NFB) * NTILE;
        int n  = n0 + tid;
        int rem = min(NTILE, N - n0);   // always 48 (N % NTILE == 0)

        if (tid < NTILE && n < N) {
            const float4* X4 = reinterpret_cast<const float4*>(X) + (size_t)n * 3;
            float4 xa = X4[0], xb = X4[1], xc = X4[2];
            float ax[4][3] = {
                {xa.x, xa.y, xa.z}, {xa.w, xb.x, xb.y},
                {xb.z, xb.w, xc.x}, {xc.y, xc.z, xc.w}
            };
            float R[3][3];
            make_frame(ax[0], ax[1], ax[2], R);

#pragma unroll
            for (int i = 0; i < 3; i++)
#pragma unroll
                for (int j = 0; j < 3; j++)
                    sm[SV_TROT + tid * 9 + 3 * i + j] = R[i][j];
            sm[SV_TTR + tid * 3 + 0] = ax[1][0];
            sm[SV_TTR + tid * 3 + 1] = ax[1][1];
            sm[SV_TTR + tid * 3 + 2] = ax[1][2];
            sm[SV_B + tid] = (float)batch_id[n];
            sm[SV_C + tid] = (float)chain[n];

            bool start = (n == 0) || (batch_id[n] != batch_id[n - 1]);
            float prev0 = 0.f, prev1 = 0.f, prev2 = 0.f;
            if (n > 0) {
                const float* xp = X + (size_t)(n - 1) * 12 + 9;
                prev0 = xp[0]; prev1 = xp[1]; prev2 = xp[2];
            }
            float* wv = sm + SV_V + tid * 76;
#pragma unroll
            for (int a = 0; a < 4; a++) {
                float dx, dy, dz;
                if (start) { dx = dy = dz = 0.f; }
                else {
                    float px, py, pz;
                    if (a == 0) { px = prev0; py = prev1; pz = prev2; }
                    else        { px = ax[a-1][0]; py = ax[a-1][1]; pz = ax[a-1][2]; }
                    dx = ax[a][0] - px; dy = ax[a][1] - py; dz = ax[a][2] - pz;
                }
                float l0 = R[0][0]*dx + R[1][0]*dy + R[2][0]*dz;
                float l1 = R[0][1]*dx + R[1][1]*dy + R[2][1]*dz;
                float l2 = R[0][2]*dx + R[1][2]*dy + R[2][2]*dz;
                dec3(wv + a * 19, l0, l1, l2);
            }
        }
        __syncthreads();

        if (tid == 0 && rem > 0) {
            tma_fence();
            tma_bulk_store(out + OFF_V + (long long)n0 * 76,     smBase + SV_V * 4u,    (uint32_t)(rem * 76 * 4));
            tma_bulk_store(out + OFF_TROT + (long long)n0 * 9,   smBase + SV_TROT * 4u, (uint32_t)(rem * 9 * 4));
            tma_bulk_store(out + OFF_TTRANS + (long long)n0 * 3, smBase + SV_TTR * 4u,  (uint32_t)(rem * 3 * 4));
            tma_bulk_store(out + OFF_BATCH + n0,                 smBase + SV_B * 4u,    (uint32_t)(rem * 4));
            tma_bulk_store(out + OFF_CHAIN + n0,                 smBase + SV_C * 4u,    (uint32_t)(rem * 4));
            tma_commit();
            tma_wait_read0();
        }
    } else {
        // ------------------------------------------------ fill + misc role (FIRST)
        const unsigned KN = KF * (unsigned)N, G2 = 2u * KN, uET = (unsigned)E + G2, KB = KF * NB;
        const unsigned zelems = G2 * (unsigned)EW;               // zero-region floats
        const unsigned CHUNKF = TILE * EW;                       // 5112 floats = 20448 B
        const unsigned nChunk = zelems / CHUNKF;
        const unsigned tailF  = zelems - nChunk * CHUNKF;        // 0 for these shapes
        const long long zbase = OFF_E + (long long)E * EW;

        unsigned fb = (unsigned)bid;

        for (int i = tid; i < (int)CHUNKF; i += BLK) sm[i] = 0.f;
        __syncthreads();

        if (tid == 0) {
            tma_fence();
            for (unsigned c = fb; c < nChunk; c += NFB)
                tma_bulk_store(out + zbase + (long long)c * CHUNKF, smBase, CHUNKF * 4u);
            if (fb == 0 && tailF)
                tma_bulk_store(out + zbase + (long long)nChunk * CHUNKF, smBase, tailF * 4u);
            tma_commit();
        }

        // misc tails (scalar; ~2.5M elements total)
        const unsigned szA = G2 * 9u;
        const unsigned szB = G2 * 3u;
        const unsigned szC = 2u * G2;
        const unsigned szD = KB;
        const unsigned szE_ = KB;
        const unsigned szF = KB * 9u;
        const unsigned szG = KB * 3u;
        const unsigned szH = KB * 76u;
        const unsigned TOT = szA + szB + szC + szD + szE_ + szF + szG + szH;

        const unsigned bTTSROT = (unsigned)OFF_TTSROT + (unsigned)E * 9u;
        const unsigned bTTSTR  = (unsigned)OFF_TTSTRANS + (unsigned)E * 3u;
        const unsigned bEIDX   = (unsigned)OFF_EIDX;
        const unsigned bBATCH  = (unsigned)OFF_BATCH + (unsigned)N;
        const unsigned bCHAIN  = (unsigned)OFF_CHAIN + (unsigned)N;
        const unsigned bTROT   = (unsigned)OFF_TROT + (unsigned)N * 9u;
        const unsigned bTTRANS = (unsigned)OFF_TTRANS + (unsigned)N * 3u;
        const unsigned bV      = (unsigned)OFF_V + (unsigned)N * 76u;
        const unsigned uN = (unsigned)N, uE = (unsigned)E;

        unsigned stride = (unsigned)NFB * BLK;
        for (unsigned j0 = fb * BLK + tid; j0 < TOT; j0 += stride) {
            unsigned j = j0;
            unsigned idx; float v;
            if (j < szA) {
                unsigned c = j % 9u;
                idx = bTTSROT + j; v = (c == 0u || c == 4u || c == 8u) ? 1.f : 0.f;
            } else if ((j -= szA) < szB) {
                idx = bTTSTR + j; v = 0.f;
            } else if ((j -= szB) < szC) {
                if (j < G2) {
                    v = (j < KN) ? (float)(uN + (unsigned)batch_id[j % uN] + (j / uN) * NB)
                                 : (float)((j - KN) % uN);
                    idx = bEIDX + uE + j;
                } else {
                    unsigned t = j - G2;
                    v = (t < KN) ? (float)(t % uN)
                                 : (float)(uN + (unsigned)batch_id[(t - KN) % uN] + ((t - KN) / uN) * NB);
                    idx = bEIDX + uET + uE + t;
                }
            } else if ((j -= szC) < szD) {
                idx = bBATCH + j; v = (float)(j % NB);
            } else if ((j -= szD) < szE_) {
                idx = bCHAIN + j; v = 1001.f;
            } else if ((j -= szE_) < szF) {
                unsigned c = j % 9u;
                idx = bTROT + j; v = (c == 0u || c == 4u || c == 8u) ? 1.f : 0.f;
            } else if ((j -= szF) < szG) {
                idx = bTTRANS + j; v = 0.f;
            } else {
                j -= szG;
                unsigned r = j / 76u, c = j % 76u;
                unsigned k = r / NB;
                unsigned m = (c < 38u) ? c : c - 38u;
                double f = exp(-(double)(2u * m) * 9.210340371976184 / 76.0);
                double ang = (double)k * f;
                idx = bV + j; v = (float)((c < 38u) ? cos(ang) : sin(ang));
            }
            out[idx] = v;
        }

        if (tid == 0) tma_wait_read0();
    }
}

// ---------------------------------------------------------------------------
extern "C" void kernel_launch(void* const* d_in, const int* in_sizes, int n_in,
                              void* d_out, int out_size) {
    const float* X        = (const float*)d_in[0];
    const int*   node_idx = (const int*)d_in[1];
    const int*   eix      = (const int*)d_in[2];
    const int*   batch_id = (const int*)d_in[3];
    const int*   chain    = (const int*)d_in[4];
    float* out = (float*)d_out;

    int N = in_sizes[0] / 12;
    int E = in_sizes[2] / 2;
    int NT = N + KF * NB;
    int G2 = 2 * KF * N;
    int ET = E + G2;

    long long OFF_V        = 0;
    long long OFF_E        = OFF_V + (long long)NT * 76;
    long long OFF_TROT     = OFF_E + (long long)ET * EW;
    long long OFF_TTRANS   = OFF_TROT + (long long)NT * 9;
    long long OFF_TTSROT   = OFF_TTRANS + (long long)NT * 3;
    long long OFF_TTSTRANS = OFF_TTSROT + (long long)ET * 9;
    long long OFF_BATCH    = OFF_TTSTRANS + (long long)ET * 3;
    long long OFF_EIDX     = OFF_BATCH + NT;
    long long OFF_CHAIN    = OFF_EIDX + 2LL * ET;

    int nEB = (E + TILE - 1) / TILE;   // 600000/24 = 25000
    int nNB = (N + NTILE - 1) / NTILE; // 30000/48 = 625
    int grid = NFB + nNB + nEB;
    int smem = SM_TOTAL * (int)sizeof(float);   // 21600 B

    static bool attr_done = false;
    if (!attr_done) {
        cudaFuncSetAttribute(fused_kernel, cudaFuncAttributeMaxDynamicSharedMemorySize, smem);
        attr_done = true;
    }

    fused_kernel<<<grid, BLK, smem>>>(X, node_idx, eix, batch_id, chain, out,
                                      N, E, nEB, nNB,
                                      OFF_V, OFF_E, OFF_TROT, OFF_TTRANS,
                                      OFF_TTSROT, OFF_TTSTRANS,
                                      OFF_BATCH, OFF_EIDX, OFF_CHAIN);
}

// round 17
// speedup vs baseline: 1.5362x; 1.0100x over previous
#include <cuda_runtime.h>
#include <math.h>
#include <stdint.h>

// GeoFeaturizer for GB300 (sm_103a). B=8 batches, K=3 virtual frames (fixed).
#define NB 8
#define KF 3
#define TILE 16        // edges per edge-block (4 threads per edge, blockDim=64: all active)
#define NTILE 32       // nodes per node-block
#define EW 213         // edge feature width
#define NFB 888        // fill/misc blocks (scheduled FIRST)
#define BLK 64

// pos-embedding freqs: 10000^(-j/8) = 10^(-j/2)
__constant__ float c_posfreq[8] = {
    1.0f, 0.31622776601683794f, 0.1f, 0.031622776601683794f,
    0.01f, 0.0031622776601683794f, 0.001f, 0.00031622776601683794f
};

// ---- TMA bulk-store helpers (smem -> gmem, L1-bypassing) ----
__device__ __forceinline__ void tma_bulk_store(void* gptr, uint32_t saddr, uint32_t bytes) {
    asm volatile("cp.async.bulk.global.shared::cta.bulk_group [%0], [%1], %2;"
                 :: "l"(gptr), "r"(saddr), "r"(bytes) : "memory");
}
__device__ __forceinline__ void tma_fence() {
    asm volatile("fence.proxy.async.shared::cta;" ::: "memory");
}
__device__ __forceinline__ void tma_commit() {
    asm volatile("cp.async.bulk.commit_group;" ::: "memory");
}
__device__ __forceinline__ void tma_wait_read0() {
    asm volatile("cp.async.bulk.wait_group.read 0;" ::: "memory");
}

__device__ __forceinline__ float ex2(float x) {
    float r;
    asm("ex2.approx.ftz.f32 %0, %1;" : "=f"(r) : "f"(x));
    return r;
}

// decouple(): 3 direction comps + 16 RBF. RBF via exp2: exp(-u^2)=2^(-(u*sqrt(log2 e))^2).
__device__ __forceinline__ void dec3(float* __restrict__ w, float x, float y, float z) {
    float sq   = x*x + y*y + z*z;
    float norm = sqrtf(sq + 1e-12f);
    float inv  = (norm < 1e-4f) ? 0.f : __fdividef(1.f, norm + 1e-6f);
    w[0] = x * inv; w[1] = y * inv; w[2] = z * inv;
    float a2 = 0.96089792702916f * norm;          // 0.8*sqrt(log2 e)
#pragma unroll
    for (int r = 0; r < 16; r++) {
        float u = a2 - (float)r * 1.2811972360389f;  // (16/15)*sqrt(log2 e)
        w[3 + r] = ex2(-u * u);
    }
}

// f32 Cody-Waite reduction then fast sin/cos (|ang| <= ~3.2e4).
__device__ __forceinline__ void fast_sincos(float ang, float* s, float* c) {
    const float INV2PI = 0.15915494309189535f;
    const float PI2_HI = 6.28318548202514648f;
    const float PI2_LO = -1.74845553146357e-07f;
    float k = rintf(ang * INV2PI);
    float r = fmaf(-k, PI2_HI, ang);
    r = fmaf(-k, PI2_LO, r);
    *s = __sinf(r);
    *c = __cosf(r);
}

// Frame from atoms 0,1,2 (N, CA, C). R is the reference's stored R (= M^T).
__device__ __forceinline__ void make_frame(const float a0[3], const float a1[3], const float a2v[3],
                                           float R[3][3]) {
    float nx = a0[0] - a1[0], ny_ = a0[1] - a1[1], nz_ = a0[2] - a1[2];
    float cx = a2v[0] - a1[0], cy  = a2v[1] - a1[1], cz  = a2v[2] - a1[2];
    const float EPSf = 1e-20f;
    float nrm  = sqrtf(EPSf + cx*cx + cy*cy);
    float s1 = -cy / nrm, c1 = cx / nrm;
    float nrm2 = sqrtf(EPSf + cx*cx + cy*cy + cz*cz);
    float s2 = cz / nrm2;
    float c2 = sqrtf(cx*cx + cy*cy) / nrm2;
    float Rc[3][3] = {
        { c2*c1, -c2*s1, s2 },
        { s1,     c1,    0.f},
        {-s2*c1,  s2*s1, c2 }
    };
    float nr1 = Rc[1][0]*nx + Rc[1][1]*ny_;
    float nr2 = Rc[2][0]*nx + Rc[2][1]*ny_ + Rc[2][2]*nz_;
    float nrm3 = sqrtf(EPSf + nr1*nr1 + nr2*nr2);
    float sn = -nr2 / nrm3, cn = nr1 / nrm3;
    float M1[3], M2[3];
#pragma unroll
    for (int j = 0; j < 3; j++) {
        M1[j] = cn * Rc[1][j] - sn * Rc[2][j];
        M2[j] = sn * Rc[1][j] + cn * Rc[2][j];
    }
#pragma unroll
    for (int j = 0; j < 3; j++) {
        R[j][0] = Rc[0][j];
        R[j][1] = M1[j];
        R[j][2] = M2[j];
    }
}

// edge smem layout (floats): [0, TILE*EW) rows; TILE*9 rot; TILE*3 trans
#define SM_ROT   (TILE * EW)                // 3408
#define SM_TRANS (SM_ROT + TILE * 9)        // 3552
#define SM_TOTAL (SM_TRANS + TILE * 3)      // 3600 floats = 14400 B

// node smem layout (floats) — must fit in SM_TOTAL
#define SV_V     0
#define SV_TROT  (NTILE * 76)               // 2432
#define SV_TTR   (SV_TROT + NTILE * 9)      // 2720
#define SV_B     (SV_TTR + NTILE * 3)       // 2816
#define SV_C     (SV_B + NTILE)             // 2848 (end 2880 < 3600)

// ---------------------------------------------------------------------------
// Role order by bid: [0,NFB) fill+misc | [NFB,NFB+nNB) node | rest edge.
// ---------------------------------------------------------------------------
__global__ void __launch_bounds__(BLK, 15)
fused_kernel(const float* __restrict__ X,
             const int*  __restrict__ node_idx,
             const int*  __restrict__ eix,       // (2, E) row-major
             const int*  __restrict__ batch_id,
             const int*  __restrict__ chain,
             float* __restrict__ out,
             int N, int E, int nEB, int nNB,
             long long OFF_V, long long OFF_E, long long OFF_TROT,
             long long OFF_TTRANS, long long OFF_TTSROT, long long OFF_TTSTRANS,
             long long OFF_BATCH, long long OFF_EIDX, long long OFF_CHAIN) {
    extern __shared__ float sm[];
    int tid = threadIdx.x;
    int bid = blockIdx.x;
    const int ET = E + 2 * KF * N;
    uint32_t smBase = (uint32_t)__cvta_generic_to_shared(sm);

    if (bid >= NFB + nNB) {
        // ------------------------------------------------ edge role (E % TILE == 0)
        int eSlot = tid >> 2;          // 0..15 (all active with BLK=64)
        int sub   = tid & 3;           // 0..3
        int e0 = (bid - NFB - nNB) * TILE;
        int e  = e0 + eSlot;

        {
            float* w = sm + eSlot * EW;
            int s = min(max(eix[e], 0), N - 1);
            int d = min(max(eix[E + e], 0), N - 1);

            const float4* Xs4 = reinterpret_cast<const float4*>(X) + (size_t)s * 3;
            const float4* Xd4 = reinterpret_cast<const float4*>(X) + (size_t)d * 3;
            float4 sa = Xs4[0], sb = Xs4[1], sc = Xs4[2];
            float4 da = Xd4[0], db = Xd4[1], dc = Xd4[2];
            float P[8][3] = {
                {sa.x, sa.y, sa.z}, {sa.w, sb.x, sb.y}, {sb.z, sb.w, sc.x}, {sc.y, sc.z, sc.w},
                {da.x, da.y, da.z}, {da.w, db.x, db.y}, {db.z, db.w, dc.x}, {dc.y, dc.z, dc.w}
            };

            float Rs[3][3];
            make_frame(P[0], P[1], P[2], Rs);
            float ts[3] = {P[1][0], P[1][1], P[1][2]};

            // each sub: 2 of the 8 atom dec3s (cols 0..151)
#pragma unroll
            for (int k = 0; k < 2; k++) {
                int a8 = 2 * sub + k;
                float q0 = P[a8][0] - ts[0], q1 = P[a8][1] - ts[1], q2 = P[a8][2] - ts[2];
                float l0 = Rs[0][0]*q0 + Rs[1][0]*q1 + Rs[2][0]*q2;
                float l1 = Rs[0][1]*q0 + Rs[1][1]*q1 + Rs[2][1]*q2;
                float l2 = Rs[0][2]*q0 + Rs[1][2]*q1 + Rs[2][2]*q2;
                dec3(w + a8 * 19, l0, l1, l2);
            }

            if (sub == 0) {
                // Q = Rs^T Rd; E_quant (cols 152..160) = Q; Tts_rot staging = Q^T
                float Rd[3][3];
                make_frame(P[4], P[5], P[6], Rd);
                float Q[3][3];
#pragma unroll
                for (int i = 0; i < 3; i++)
#pragma unroll
                    for (int j = 0; j < 3; j++)
                        Q[i][j] = Rs[0][i]*Rd[0][j] + Rs[1][i]*Rd[1][j] + Rs[2][i]*Rd[2][j];
#pragma unroll
                for (int i = 0; i < 3; i++)
#pragma unroll
                    for (int j = 0; j < 3; j++) {
                        w[152 + 3 * i + j] = Q[i][j];
                        sm[SM_ROT + eSlot * 9 + 3 * j + i] = Q[i][j];
                    }
            } else if (sub == 1) {
                // tts = Rd^T (t_src - t_dst); E_trans (cols 161..179)
                float Rd[3][3];
                make_frame(P[4], P[5], P[6], Rd);
                float dt0 = ts[0] - P[5][0], dt1 = ts[1] - P[5][1], dt2 = ts[2] - P[5][2];
                float t0 = Rd[0][0]*dt0 + Rd[1][0]*dt1 + Rd[2][0]*dt2;
                float t1 = Rd[0][1]*dt0 + Rd[1][1]*dt1 + Rd[2][1]*dt2;
                float t2 = Rd[0][2]*dt0 + Rd[1][2]*dt1 + Rd[2][2]*dt2;
                dec3(w + 161, t0, t1, t2);
                sm[SM_TRANS + eSlot * 3 + 0] = t0;
                sm[SM_TRANS + eSlot * 3 + 1] = t1;
                sm[SM_TRANS + eSlot * 3 + 2] = t2;
            } else if (sub == 2) {
                // pos embedding (cols 180..195)
                float dd = (float)(s - d);
#pragma unroll
                for (int j = 0; j < 8; j++) {
                    float ang = __fmul_rn(dd, c_posfreq[j]);
                    float si, co;
                    fast_sincos(ang, &si, &co);
                    w[180 + j] = co;
                    w[188 + j] = si;
                }
            } else {
                // E_bias (cols 196..212) + eidx outputs
                float bb = (float)(node_idx[s] - node_idx[d]);
                float nb = sqrtf(bb * bb + 1e-12f);
                float ib = (nb < 1e-4f) ? 0.f : __fdividef(1.f, nb + 1e-6f);
                w[196] = bb * ib;
                float ab = 0.96089792702916f * nb;
#pragma unroll
                for (int r = 0; r < 16; r++) {
                    float u = ab - (float)r * 1.2811972360389f;
                    w[197 + r] = ex2(-u * u);
                }
                out[OFF_EIDX + e]      = (float)eix[e];
                out[OFF_EIDX + ET + e] = (float)eix[E + e];
            }
        }
        __syncthreads();

        if (tid == 0) {
            tma_fence();
            tma_bulk_store(out + OFF_E + (long long)e0 * EW,       smBase,                  TILE * EW * 4u);
            tma_bulk_store(out + OFF_TTSROT + (long long)e0 * 9,   smBase + SM_ROT * 4u,    TILE * 9 * 4u);
            tma_bulk_store(out + OFF_TTSTRANS + (long long)e0 * 3, smBase + SM_TRANS * 4u,  TILE * 3 * 4u);
            tma_commit();
            tma_wait_read0();
        }
    } else if (bid >= NFB) {
        // ------------------------------------------------ node role (32 nodes/block)
        int n0 = (bid - NFB) * NTILE;
        int n  = n0 + tid;
        int rem = min(NTILE, N - n0);   // 32 or 16 (tail); rem*4 stays mult of 16B

        if (tid < NTILE && n < N) {
            const float4* X4 = reinterpret_cast<const float4*>(X) + (size_t)n * 3;
            float4 xa = X4[0], xb = X4[1], xc = X4[2];
            float ax[4][3] = {
                {xa.x, xa.y, xa.z}, {xa.w, xb.x, xb.y},
                {xb.z, xb.w, xc.x}, {xc.y, xc.z, xc.w}
            };
            float R[3][3];
            make_frame(ax[0], ax[1], ax[2], R);

#pragma unroll
            for (int i = 0; i < 3; i++)
#pragma unroll
                for (int j = 0; j < 3; j++)
                    sm[SV_TROT + tid * 9 + 3 * i + j] = R[i][j];
            sm[SV_TTR + tid * 3 + 0] = ax[1][0];
            sm[SV_TTR + tid * 3 + 1] = ax[1][1];
            sm[SV_TTR + tid * 3 + 2] = ax[1][2];
            sm[SV_B + tid] = (float)batch_id[n];
            sm[SV_C + tid] = (float)chain[n];

            bool start = (n == 0) || (batch_id[n] != batch_id[n - 1]);
            float prev0 = 0.f, prev1 = 0.f, prev2 = 0.f;
            if (n > 0) {
                const float* xp = X + (size_t)(n - 1) * 12 + 9;
                prev0 = xp[0]; prev1 = xp[1]; prev2 = xp[2];
            }
            float* wv = sm + SV_V + tid * 76;
#pragma unroll
            for (int a = 0; a < 4; a++) {
                float dx, dy, dz;
                if (start) { dx = dy = dz = 0.f; }
                else {
                    float px, py, pz;
                    if (a == 0) { px = prev0; py = prev1; pz = prev2; }
                    else        { px = ax[a-1][0]; py = ax[a-1][1]; pz = ax[a-1][2]; }
                    dx = ax[a][0] - px; dy = ax[a][1] - py; dz = ax[a][2] - pz;
                }
                float l0 = R[0][0]*dx + R[1][0]*dy + R[2][0]*dz;
                float l1 = R[0][1]*dx + R[1][1]*dy + R[2][1]*dz;
                float l2 = R[0][2]*dx + R[1][2]*dy + R[2][2]*dz;
                dec3(wv + a * 19, l0, l1, l2);
            }
        }
        __syncthreads();

        if (tid == 0 && rem > 0) {
            tma_fence();
            tma_bulk_store(out + OFF_V + (long long)n0 * 76,     smBase + SV_V * 4u,    (uint32_t)(rem * 76 * 4));
            tma_bulk_store(out + OFF_TROT + (long long)n0 * 9,   smBase + SV_TROT * 4u, (uint32_t)(rem * 9 * 4));
            tma_bulk_store(out + OFF_TTRANS + (long long)n0 * 3, smBase + SV_TTR * 4u,  (uint32_t)(rem * 3 * 4));
            tma_bulk_store(out + OFF_BATCH + n0,                 smBase + SV_B * 4u,    (uint32_t)(rem * 4));
            tma_bulk_store(out + OFF_CHAIN + n0,                 smBase + SV_C * 4u,    (uint32_t)(rem * 4));
            tma_commit();
            tma_wait_read0();
        }
    } else {
        // ------------------------------------------------ fill + misc role (FIRST)
        const unsigned KN = KF * (unsigned)N, G2 = 2u * KN, uET = (unsigned)E + G2, KB = KF * NB;
        const unsigned zelems = G2 * (unsigned)EW;               // zero-region floats
        const unsigned CHUNKF = TILE * EW;                       // 3408 floats = 13632 B
        const unsigned nChunk = zelems / CHUNKF;
        const unsigned tailF  = zelems - nChunk * CHUNKF;        // mult of 4
        const long long zbase = OFF_E + (long long)E * EW;

        unsigned fb = (unsigned)bid;

        for (int i = tid; i < (int)CHUNKF; i += BLK) sm[i] = 0.f;
        __syncthreads();

        if (tid == 0) {
            tma_fence();
            for (unsigned c = fb; c < nChunk; c += NFB)
                tma_bulk_store(out + zbase + (long long)c * CHUNKF, smBase, CHUNKF * 4u);
            if (fb == 0 && tailF)
                tma_bulk_store(out + zbase + (long long)nChunk * CHUNKF, smBase, tailF * 4u);
            tma_commit();
        }

        // misc tails (scalar; ~2.5M elements total)
        const unsigned szA = G2 * 9u;
        const unsigned szB = G2 * 3u;
        const unsigned szC = 2u * G2;
        const unsigned szD = KB;
        const unsigned szE_ = KB;
        const unsigned szF = KB * 9u;
        const unsigned szG = KB * 3u;
        const unsigned szH = KB * 76u;
        const unsigned TOT = szA + szB + szC + szD + szE_ + szF + szG + szH;

        const unsigned bTTSROT = (unsigned)OFF_TTSROT + (unsigned)E * 9u;
        const unsigned bTTSTR  = (unsigned)OFF_TTSTRANS + (unsigned)E * 3u;
        const unsigned bEIDX   = (unsigned)OFF_EIDX;
        const unsigned bBATCH  = (unsigned)OFF_BATCH + (unsigned)N;
        const unsigned bCHAIN  = (unsigned)OFF_CHAIN + (unsigned)N;
        const unsigned bTROT   = (unsigned)OFF_TROT + (unsigned)N * 9u;
        const unsigned bTTRANS = (unsigned)OFF_TTRANS + (unsigned)N * 3u;
        const unsigned bV      = (unsigned)OFF_V + (unsigned)N * 76u;
        const unsigned uN = (unsigned)N, uE = (unsigned)E;

        unsigned stride = (unsigned)NFB * BLK;
        for (unsigned j0 = fb * BLK + tid; j0 < TOT; j0 += stride) {
            unsigned j = j0;
            unsigned idx; float v;
            if (j < szA) {
                unsigned c = j % 9u;
                idx = bTTSROT + j; v = (c == 0u || c == 4u || c == 8u) ? 1.f : 0.f;
            } else if ((j -= szA) < szB) {
                idx = bTTSTR + j; v = 0.f;
            } else if ((j -= szB) < szC) {
                if (j < G2) {
                    v = (j < KN) ? (float)(uN + (unsigned)batch_id[j % uN] + (j / uN) * NB)
                                 : (float)((j - KN) % uN);
                    idx = bEIDX + uE + j;
                } else {
                    unsigned t = j - G2;
                    v = (t < KN) ? (float)(t % uN)
                                 : (float)(uN + (unsigned)batch_id[(t - KN) % uN] + ((t - KN) / uN) * NB);
                    idx = bEIDX + uET + uE + t;
                }
            } else if ((j -= szC) < szD) {
                idx = bBATCH + j; v = (float)(j % NB);
            } else if ((j -= szD) < szE_) {
                idx = bCHAIN + j; v = 1001.f;
            } else if ((j -= szE_) < szF) {
                unsigned c = j % 9u;
                idx = bTROT + j; v = (c == 0u || c == 4u || c == 8u) ? 1.f : 0.f;
            } else if ((j -= szF) < szG) {
                idx = bTTRANS + j; v = 0.f;
            } else {
                j -= szG;
                unsigned r = j / 76u, c = j % 76u;
                unsigned k = r / NB;
                unsigned m = (c < 38u) ? c : c - 38u;
                double f = exp(-(double)(2u * m) * 9.210340371976184 / 76.0);
                double ang = (double)k * f;
                idx = bV + j; v = (float)((c < 38u) ? cos(ang) : sin(ang));
            }
            out[idx] = v;
        }

        if (tid == 0) tma_wait_read0();
    }
}

// ---------------------------------------------------------------------------
extern "C" void kernel_launch(void* const* d_in, const int* in_sizes, int n_in,
                              void* d_out, int out_size) {
    const float* X        = (const float*)d_in[0];
    const int*   node_idx = (const int*)d_in[1];
    const int*   eix      = (const int*)d_in[2];
    const int*   batch_id = (const int*)d_in[3];
    const int*   chain    = (const int*)d_in[4];
    float* out = (float*)d_out;

    int N = in_sizes[0] / 12;
    int E = in_sizes[2] / 2;
    int NT = N + KF * NB;
    int G2 = 2 * KF * N;
    int ET = E + G2;

    long long OFF_V        = 0;
    long long OFF_E        = OFF_V + (long long)NT * 76;
    long long OFF_TROT     = OFF_E + (long long)ET * EW;
    long long OFF_TTRANS   = OFF_TROT + (long long)NT * 9;
    long long OFF_TTSROT   = OFF_TTRANS + (long long)NT * 3;
    long long OFF_TTSTRANS = OFF_TTSROT + (long long)ET * 9;
    long long OFF_BATCH    = OFF_TTSTRANS + (long long)ET * 3;
    long long OFF_EIDX     = OFF_BATCH + NT;
    long long OFF_CHAIN    = OFF_EIDX + 2LL * ET;

    int nEB = (E + TILE - 1) / TILE;   // 600000/16 = 37500
    int nNB = (N + NTILE - 1) / NTILE; // ceil(30000/32) = 938
    int grid = NFB + nNB + nEB;
    int smem = SM_TOTAL * (int)sizeof(float);   // 14400 B

    static bool attr_done = false;
    if (!attr_done) {
        cudaFuncSetAttribute(fused_kernel, cudaFuncAttributeMaxDynamicSharedMemorySize, smem);
        attr_done = true;
    }

    fused_kernel<<<grid, BLK, smem>>>(X, node_idx, eix, batch_id, chain, out,
                                      N, E, nEB, nNB,
                                      OFF_V, OFF_E, OFF_TROT, OFF_TTRANS,
                                      OFF_TTSROT, OFF_TTSTRANS,
                                      OFF_BATCH, OFF_EIDX, OFF_CHAIN);
}